// round 14
// baseline (speedup 1.0000x reference)
#include <cuda_runtime.h>
#include <cuda_fp16.h>
#include <stdint.h>

#define N_B   8
#define SEQ   2048
#define EMB   512
#define H     8
#define HD    64
#define NROWS (N_B*SEQ)
#define NH    (N_B*H)

// -------- scratch (no cudaMalloc allowed) --------
__device__ uint32_t g_wh[4*256*EMB];                                   // [slot][kp][n]
__device__ uint32_t g_xh[(size_t)3*NROWS*256], g_xl[(size_t)3*NROWS*256]; // [inp][row][kp]
__device__ uint32_t g_qh[(size_t)NH*SEQ*32], g_ql[(size_t)NH*SEQ*32];
__device__ uint32_t g_kh[(size_t)NH*SEQ*32];
__device__ uint32_t g_vh[(size_t)NH*(SEQ/2)*64];
__device__ uint32_t g_aoh[(size_t)NROWS*256], g_aol[(size_t)NROWS*256];   // [row][kp]

// ---------------- helpers ----------------
__device__ __forceinline__ uint32_t pack2h(__half a, __half b) {
    return ((uint32_t)__half_as_ushort(b) << 16) | (uint32_t)__half_as_ushort(a);
}
__device__ __forceinline__ void split_packh(float x0, float x1, uint32_t &hi, uint32_t &lo) {
    __half h0 = __float2half_rn(x0), h1 = __float2half_rn(x1);
    __half l0 = __float2half_rn(x0 - __half2float(h0));
    __half l1 = __float2half_rn(x1 - __half2float(h1));
    hi = pack2h(h0, h1); lo = pack2h(l0, l1);
}
__device__ __forceinline__ uint32_t packh_hi(float x0, float x1) {
    return pack2h(__float2half_rn(x0), __float2half_rn(x1));
}
__device__ __forceinline__ void mmah(float c[4], const uint32_t a[4], const uint32_t b[2]) {
    asm volatile(
      "mma.sync.aligned.m16n8k16.row.col.f32.f16.f16.f32 "
      "{%0,%1,%2,%3},{%4,%5,%6,%7},{%8,%9},{%0,%1,%2,%3};\n"
      : "+f"(c[0]), "+f"(c[1]), "+f"(c[2]), "+f"(c[3])
      : "r"(a[0]), "r"(a[1]), "r"(a[2]), "r"(a[3]), "r"(b[0]), "r"(b[1]));
}
__device__ __forceinline__ void cpa16(void* s, const void* g) {
    uint32_t sa = (uint32_t)__cvta_generic_to_shared(s);
    asm volatile("cp.async.cg.shared.global [%0], [%1], 16;" :: "r"(sa), "l"(g) : "memory");
}
__device__ __forceinline__ float ex2f(float x) {
    float r; asm("ex2.approx.ftz.f32 %0, %1;" : "=f"(r) : "f"(x)); return r;
}
#define CPCOMMIT() asm volatile("cp.async.commit_group;" ::: "memory")
#define CPWAIT(n)  asm volatile("cp.async.wait_group %0;" :: "n"(n) : "memory")
#define CPA_ARRIVE(a) asm volatile("cp.async.mbarrier.arrive.noinc.shared.b64 [%0];" :: "r"(a) : "memory")
#define MBAR_INIT(a, c)   asm volatile("mbarrier.init.shared.b64 [%0], %1;" :: "r"(a), "r"(c) : "memory")
#define MBAR_ARRIVE(a)    asm volatile("mbarrier.arrive.shared.b64 _, [%0];" :: "r"(a) : "memory")
#define MBAR_WAIT(a, par) do { \
    asm volatile("{\n\t.reg .pred P1;\n\tWL%=:\n\t" \
        "mbarrier.try_wait.parity.acquire.cta.shared::cta.b64 P1, [%0], %1, 0x989680;\n\t" \
        "@P1 bra.uni WD%=;\n\tbra.uni WL%=;\n\tWD%=:\n\t}" \
        :: "r"(a), "r"(par) : "memory"); } while (0)

// ============================================================
// split_w: weights -> fp16 hi pairs packed along k. [slot][kp][n]
// ============================================================
__global__ __launch_bounds__(256) void split_w(
    const float* __restrict__ Wv, const float* __restrict__ Wk,
    const float* __restrict__ Wq, const float* __restrict__ Wo)
{
    const int slot = blockIdx.y;
    const float* src = (slot==0)?Wv:(slot==1)?Wk:(slot==2)?Wq:Wo;
    int i = blockIdx.x * 256 + threadIdx.x;
    int kp = i >> 9, n = i & 511;
    float x0 = src[(2*kp  ) * EMB + n];
    float x1 = src[(2*kp+1) * EMB + n];
    g_wh[(size_t)slot*256*EMB + i] = packh_hi(x0, x1);
}

// ============================================================
// split_x: inputs -> fp16 hi/lo pairs packed along k. [inp][row][kp]
// ============================================================
__global__ __launch_bounds__(256) void split_x(
    const float* __restrict__ values, const float* __restrict__ keys,
    const float* __restrict__ query)
{
    const int inp = blockIdx.y;   // 0:v 1:k 2:q
    const float* src = (inp==0)?values:(inp==1)?keys:query;
    int i = blockIdx.x * 256 + threadIdx.x;     // row*256 + kp
    int row = i >> 8, kp = i & 255;
    float2 v = *(const float2*)(src + (size_t)row*EMB + 2*kp);
    uint32_t hi, lo; split_packh(v.x, v.y, hi, lo);
    g_xh[(size_t)inp*NROWS*256 + i] = hi;
    g_xl[(size_t)inp*NROWS*256 + i] = lo;
}

// ============================================================
// fp16x2 GEMM core: A pre-split hi/lo u32, B hi-only.
// ktile 32 (16 kp), 3-stage ring, one sync/tile.
// ============================================================
#define ASTP 20       // u32 stride for A tiles (16 + 4 pad)
#define BSTP 136
#define GAH (3*128*ASTP)   // u32 per A array
#define GB  (3*16*BSTP)    // u32
#define GEMM_SMEM ((2*GAH + GB) * 4)

__device__ __forceinline__ void gemm_prefetch(
    const uint32_t* __restrict__ Xh, const uint32_t* __restrict__ Xl,
    const uint32_t* __restrict__ Wh,
    uint32_t* Ah, uint32_t* Al, uint32_t* Bh,
    int m0, int n0, int kp0, int buf, int tid)
{
    #pragma unroll
    for (int it = 0; it < 2; it++) {
        int f = tid + 256 * it;            // 0..511
        int row = f >> 2, c4 = f & 3;
        size_t ga = (size_t)(m0 + row) * 256 + kp0 + c4 * 4;
        int so = (buf*128 + row) * ASTP + c4 * 4;
        cpa16(&Ah[so], Xh + ga);
        cpa16(&Al[so], Xl + ga);
    }
    #pragma unroll
    for (int it = 0; it < 2; it++) {
        int f = tid + 256 * it;
        int row = f >> 5, c4 = f & 31;
        cpa16(&Bh[(buf*16 + row)*BSTP + c4*4], Wh + (size_t)(kp0+row)*EMB + n0 + c4*4);
    }
}

__device__ __forceinline__ void gemm_core(
    const uint32_t* __restrict__ Xh, const uint32_t* __restrict__ Xl,
    const uint32_t* __restrict__ Wh,
    uint32_t* smu, float c[2][8][4], int m0, int n0, int tid)
{
    uint32_t* Ah = smu;
    uint32_t* Al = Ah + GAH;
    uint32_t* Bh = Al + GAH;

    const int lane = tid & 31, w = tid >> 5;
    const int g = lane >> 2, cq = lane & 3;
    const int wm = (w & 3) * 32, wn = (w >> 2) * 64;

    #pragma unroll
    for (int mt = 0; mt < 2; mt++)
        #pragma unroll
        for (int nt = 0; nt < 8; nt++)
            #pragma unroll
            for (int e = 0; e < 4; e++) c[mt][nt][e] = 0.f;

    gemm_prefetch(Xh, Xl, Wh, Ah, Al, Bh, m0, n0, 0, 0, tid);
    CPCOMMIT();
    gemm_prefetch(Xh, Xl, Wh, Ah, Al, Bh, m0, n0, 16, 1, tid);
    CPCOMMIT();

    for (int t = 0; t < 16; t++) {
        CPWAIT(1);
        __syncthreads();
        if (t + 2 < 16)
            gemm_prefetch(Xh, Xl, Wh, Ah, Al, Bh, m0, n0, (t+2)*16, (t+2)%3, tid);
        CPCOMMIT();

        const int cb = t % 3;
        const int ab = cb * 128, bb = cb * 16;
        #pragma unroll
        for (int ks = 0; ks < 2; ks++) {
            uint32_t ah[2][4], al[2][4];
            #pragma unroll
            for (int mt = 0; mt < 2; mt++) {
                int r0 = (ab + wm + mt*16 + g) * ASTP + ks*8;
                int r1 = r0 + 8*ASTP;
                ah[mt][0] = Ah[r0 + cq];     ah[mt][1] = Ah[r1 + cq];
                ah[mt][2] = Ah[r0 + 4 + cq]; ah[mt][3] = Ah[r1 + 4 + cq];
                al[mt][0] = Al[r0 + cq];     al[mt][1] = Al[r1 + cq];
                al[mt][2] = Al[r0 + 4 + cq]; al[mt][3] = Al[r1 + 4 + cq];
            }
            uint32_t bh[8][2];
            #pragma unroll
            for (int nt = 0; nt < 8; nt++) {
                int nn = wn + nt*8 + g;
                int kp = bb + ks*8 + cq;
                bh[nt][0] = Bh[(kp    )*BSTP + nn];
                bh[nt][1] = Bh[(kp + 4)*BSTP + nn];
            }
            #pragma unroll
            for (int mt = 0; mt < 2; mt++)
                #pragma unroll
                for (int nt = 0; nt < 8; nt++) {
                    mmah(c[mt][nt], ah[mt], bh[nt]);
                    mmah(c[mt][nt], al[mt], bh[nt]);
                }
        }
    }
}

// ============================================================
// Projections. Q: *0.125*log2(e), hi+lo. K: hi. V: hi via shfl.
// ============================================================
__global__ __launch_bounds__(256, 2) void proj_kernel()
{
    extern __shared__ uint32_t smu[];
    const int which = blockIdx.z;   // 0:v 1:k 2:q
    const uint32_t* Xh = g_xh + (size_t)which*NROWS*256;
    const uint32_t* Xl = g_xl + (size_t)which*NROWS*256;
    const uint32_t* Wh = g_wh + (size_t)which*256*EMB;

    const int m0 = blockIdx.y * 128, n0 = blockIdx.x * 128;
    float c[2][8][4];
    gemm_core(Xh, Xl, Wh, smu, c, m0, n0, threadIdx.x);

    const int lane = threadIdx.x & 31, w = threadIdx.x >> 5;
    const int g = lane >> 2, cq = lane & 3;
    const int wm = (w & 3) * 32, wn = (w >> 2) * 64;

    if (which == 2) {
        const float post = 0.125f * 1.44269504f;
        #pragma unroll
        for (int mt = 0; mt < 2; mt++)
            #pragma unroll
            for (int half = 0; half < 2; half++) {
                int row = m0 + wm + mt*16 + g + half*8;
                int n = row >> 11, s = row & 2047;
                #pragma unroll
                for (int nt = 0; nt < 8; nt++) {
                    int col = n0 + wn + nt*8 + 2*cq;
                    int h = col >> 6, d = col & 63;
                    size_t base = ((size_t)(n*H + h)*SEQ + s)*32 + (d >> 1);
                    uint32_t hi, lo;
                    split_packh(c[mt][nt][half*2+0]*post, c[mt][nt][half*2+1]*post, hi, lo);
                    g_qh[base] = hi; g_ql[base] = lo;
                }
            }
    } else if (which == 1) {
        #pragma unroll
        for (int mt = 0; mt < 2; mt++)
            #pragma unroll
            for (int half = 0; half < 2; half++) {
                int row = m0 + wm + mt*16 + g + half*8;
                int n = row >> 11, s = row & 2047;
                #pragma unroll
                for (int nt = 0; nt < 8; nt++) {
                    int col = n0 + wn + nt*8 + 2*cq;
                    int h = col >> 6, d = col & 63;
                    size_t base = ((size_t)(n*H + h)*SEQ + s)*32 + (d >> 1);
                    g_kh[base] = packh_hi(c[mt][nt][half*2+0], c[mt][nt][half*2+1]);
                }
            }
    } else {
        #pragma unroll
        for (int mt = 0; mt < 2; mt++)
            #pragma unroll
            for (int nt = 0; nt < 8; nt++) {
                float p0 = __shfl_xor_sync(0xffffffffu, c[mt][nt][0], 4);
                float p1 = __shfl_xor_sync(0xffffffffu, c[mt][nt][1], 4);
                float p2 = __shfl_xor_sync(0xffffffffu, c[mt][nt][2], 4);
                float p3 = __shfl_xor_sync(0xffffffffu, c[mt][nt][3], 4);
                if ((g & 1) == 0) {
                    int col = n0 + wn + nt*8 + 2*cq;
                    int h = col >> 6, d = col & 63;
                    #pragma unroll
                    for (int half = 0; half < 2; half++) {
                        int row = m0 + wm + mt*16 + g + half*8;  // even
                        int n = row >> 11, s = row & 2047;
                        size_t base = ((size_t)(n*H + h)*(SEQ/2) + (s >> 1))*64 + d;
                        float m0v = c[mt][nt][half*2+0], m1v = c[mt][nt][half*2+1];
                        float q0v = (half == 0) ? p0 : p2;
                        float q1v = (half == 0) ? p1 : p3;
                        g_vh[base    ] = packh_hi(m0v, q0v);
                        g_vh[base + 1] = packh_hi(m1v, q1v);
                    }
                }
            }
    }
}

// ============================================================
// Output GEMM: out = ao @ Wo + bo  (ao pre-split by flash)
// ============================================================
__global__ __launch_bounds__(256, 2) void out_kernel(
    const float* __restrict__ bo, float* __restrict__ out)
{
    extern __shared__ uint32_t smu[];
    const int m0 = blockIdx.y * 128, n0 = blockIdx.x * 128;
    float c[2][8][4];
    gemm_core(g_aoh, g_aol, g_wh + (size_t)3*256*EMB, smu, c, m0, n0, threadIdx.x);

    const int lane = threadIdx.x & 31, w = threadIdx.x >> 5;
    const int g = lane >> 2, cq = lane & 3;
    const int wm = (w & 3) * 32, wn = (w >> 2) * 64;

    #pragma unroll
    for (int mt = 0; mt < 2; mt++)
        #pragma unroll
        for (int half = 0; half < 2; half++) {
            size_t row = m0 + wm + mt*16 + g + half*8;
            #pragma unroll
            for (int nt = 0; nt < 8; nt++) {
                int col = n0 + wn + nt*8 + 2*cq;
                float2 v = make_float2(c[mt][nt][half*2+0] + bo[col],
                                       c[mt][nt][half*2+1] + bo[col+1]);
                *(float2*)&out[row * EMB + col] = v;
            }
        }
}

// ============================================================
// Flash attention (R12): fp16x2, BQ=128, BKV=32, 4-stage
// mbarrier pipeline, no __syncthreads in loop. K/V hi-only.
// Epilogue writes pre-split ao (hi/lo).
// ============================================================
#define BQF 128
#define BKV 32
#define SFL 4
#define KSTP 36
#define VSTP 72
#define NT (SEQ/BKV)
#define FK (SFL*BKV*KSTP)
#define FV (SFL*(BKV/2)*VSTP)
#define FL_MS (FK + FV)
#define FL_MB (FL_MS + SFL*BKV)
#define FLASH_SMEM (FL_MB*4 + 64)

__device__ __forceinline__ void flash_fill(
    const uint32_t* __restrict__ Khg, const uint32_t* __restrict__ Vhg,
    const int* __restrict__ mrow, uint32_t* Kh, uint32_t* Vh,
    int* ms, int k0, int buf, int tid)
{
    int row = tid >> 3, c4 = tid & 7;
    cpa16(&Kh[(buf*BKV+row)*KSTP + c4*4], Khg + (size_t)(k0+row)*32 + c4*4);
    int vr = tid >> 4, vc = tid & 15;
    cpa16(&Vh[(buf*(BKV/2)+vr)*VSTP + vc*4], Vhg + (size_t)(k0/2+vr)*64 + vc*4);
    if (tid < 8) cpa16(&ms[buf*BKV + tid*4], mrow + k0 + tid*4);
}

__global__ __launch_bounds__(256, 2) void flash_kernel(const int* __restrict__ mask)
{
    extern __shared__ uint32_t smu[];
    uint32_t* Kh = smu;
    uint32_t* Vh = Kh + FK;
    int*      ms = (int*)(smu + FL_MS);
    const uint32_t sbF = (uint32_t)__cvta_generic_to_shared(smu);
    const uint32_t mb1 = sbF + FL_MB*4;
    const uint32_t mb2 = sbF + FL_MB*4 + 32;

    const int tid = threadIdx.x;
    const int lane = tid & 31, w = tid >> 5;
    const int g = lane >> 2, cq = lane & 3;
    const int q0 = blockIdx.x * BQF;
    const int nh = blockIdx.y;
    const int n = nh >> 3, h = nh & 7;
    const uint32_t* Qhg = g_qh + (size_t)nh * SEQ * 32;
    const uint32_t* Qlg = g_ql + (size_t)nh * SEQ * 32;
    const uint32_t* Khg = g_kh + (size_t)nh * SEQ * 32;
    const uint32_t* Vhg = g_vh + (size_t)nh * (SEQ/2) * 64;
    const int* mrow = mask + n * SEQ;
    const int rb = w * 16 + g;

    if (tid == 0) {
        #pragma unroll
        for (int s = 0; s < SFL; s++) {
            MBAR_INIT(mb1 + s*8, 256);
            MBAR_INIT(mb2 + s*8, 256);
        }
    }
    __syncthreads();

    flash_fill(Khg, Vhg, mrow, Kh, Vh, ms, 0, 0, tid);
    CPA_ARRIVE(mb1 + 0*8);
    flash_fill(Khg, Vhg, mrow, Kh, Vh, ms, BKV, 1, tid);
    CPA_ARRIVE(mb1 + 1*8);

    uint32_t qh[4][4], ql[4][4];
    {
        const int r0 = q0 + rb, r1 = r0 + 8;
        #pragma unroll
        for (int ks = 0; ks < 4; ks++) {
            int d0 = ks*8 + cq, d1 = ks*8 + 4 + cq;
            qh[ks][0] = Qhg[(size_t)r0*32 + d0];
            qh[ks][1] = Qhg[(size_t)r1*32 + d0];
            qh[ks][2] = Qhg[(size_t)r0*32 + d1];
            qh[ks][3] = Qhg[(size_t)r1*32 + d1];
            ql[ks][0] = Qlg[(size_t)r0*32 + d0];
            ql[ks][1] = Qlg[(size_t)r1*32 + d0];
            ql[ks][2] = Qlg[(size_t)r0*32 + d1];
            ql[ks][3] = Qlg[(size_t)r1*32 + d1];
        }
    }

    float acc[8][4];
    float mi[2] = {-1e30f, -1e30f}, li[2] = {0.f, 0.f};
    #pragma unroll
    for (int nt = 0; nt < 8; nt++)
        #pragma unroll
        for (int e = 0; e < 4; e++) acc[nt][e] = 0.f;

    for (int t = 0; t < NT; t++) {
        const int f = t + 2;
        if (f < NT) {
            const int s = f & 3;
            if (t >= 2) MBAR_WAIT(mb2 + s*8, ((t - 2) >> 2) & 1);
            flash_fill(Khg, Vhg, mrow, Kh, Vh, ms, f*BKV, s, tid);
            CPA_ARRIVE(mb1 + s*8);
        }

        const int cb = t & 3;
        MBAR_WAIT(mb1 + cb*8, (t >> 2) & 1);

        const uint32_t* KhC = Kh + cb * BKV * KSTP;
        const uint32_t* VhC = Vh + cb * (BKV/2) * VSTP;
        const int*      msC = ms + cb * BKV;

        float s[4][4];
        #pragma unroll
        for (int nt = 0; nt < 4; nt++)
            #pragma unroll
            for (int e = 0; e < 4; e++) s[nt][e] = 0.f;

        #pragma unroll
        for (int ks = 0; ks < 4; ks++) {
            int d0 = ks*8 + cq, d1 = ks*8 + 4 + cq;
            uint32_t bh[4][2];
            #pragma unroll
            for (int nt = 0; nt < 4; nt++) {
                int nn = nt*8 + g;
                bh[nt][0] = KhC[nn*KSTP + d0];
                bh[nt][1] = KhC[nn*KSTP + d1];
            }
            #pragma unroll
            for (int nt = 0; nt < 4; nt++) {
                mmah(s[nt], qh[ks], bh[nt]);
                mmah(s[nt], ql[ks], bh[nt]);
            }
        }

        float mx0 = -1e30f, mx1 = -1e30f;
        #pragma unroll
        for (int nt = 0; nt < 4; nt++) {
            #pragma unroll
            for (int j = 0; j < 2; j++) {
                int mv = msC[nt*8 + 2*cq + j];
                float v0 = mv ? s[nt][j]   : -1e30f;
                float v1 = mv ? s[nt][2+j] : -1e30f;
                s[nt][j] = v0; s[nt][2+j] = v1;
                mx0 = fmaxf(mx0, v0); mx1 = fmaxf(mx1, v1);
            }
        }
        mx0 = fmaxf(mx0, __shfl_xor_sync(0xffffffffu, mx0, 1));
        mx0 = fmaxf(mx0, __shfl_xor_sync(0xffffffffu, mx0, 2));
        mx1 = fmaxf(mx1, __shfl_xor_sync(0xffffffffu, mx1, 1));
        mx1 = fmaxf(mx1, __shfl_xor_sync(0xffffffffu, mx1, 2));

        float mn0 = fmaxf(mi[0], mx0), mn1 = fmaxf(mi[1], mx1);
        float cr0 = ex2f(mi[0] - mn0), cr1 = ex2f(mi[1] - mn1);
        float sum0 = 0.f, sum1 = 0.f;
        #pragma unroll
        for (int nt = 0; nt < 4; nt++) {
            s[nt][0] = ex2f(s[nt][0] - mn0);
            s[nt][1] = ex2f(s[nt][1] - mn0);
            s[nt][2] = ex2f(s[nt][2] - mn1);
            s[nt][3] = ex2f(s[nt][3] - mn1);
            sum0 += s[nt][0] + s[nt][1];
            sum1 += s[nt][2] + s[nt][3];
        }
        sum0 += __shfl_xor_sync(0xffffffffu, sum0, 1);
        sum0 += __shfl_xor_sync(0xffffffffu, sum0, 2);
        sum1 += __shfl_xor_sync(0xffffffffu, sum1, 1);
        sum1 += __shfl_xor_sync(0xffffffffu, sum1, 2);
        li[0] = li[0] * cr0 + sum0; mi[0] = mn0;
        li[1] = li[1] * cr1 + sum1; mi[1] = mn1;
        #pragma unroll
        for (int nt = 0; nt < 8; nt++) {
            acc[nt][0] *= cr0; acc[nt][1] *= cr0;
            acc[nt][2] *= cr1; acc[nt][3] *= cr1;
        }

        uint32_t ph[2][4], pl[2][4];
        #pragma unroll
        for (int k2 = 0; k2 < 2; k2++) {
            split_packh(s[2*k2  ][0], s[2*k2  ][1], ph[k2][0], pl[k2][0]);
            split_packh(s[2*k2  ][2], s[2*k2  ][3], ph[k2][1], pl[k2][1]);
            split_packh(s[2*k2+1][0], s[2*k2+1][1], ph[k2][2], pl[k2][2]);
            split_packh(s[2*k2+1][2], s[2*k2+1][3], ph[k2][3], pl[k2][3]);
        }

        #pragma unroll
        for (int k2 = 0; k2 < 2; k2++) {
            int sp0 = k2*8 + cq, sp1 = k2*8 + 4 + cq;
            uint32_t vh[8][2];
            #pragma unroll
            for (int nt = 0; nt < 8; nt++) {
                int dd = nt*8 + g;
                vh[nt][0] = VhC[sp0*VSTP + dd];
                vh[nt][1] = VhC[sp1*VSTP + dd];
            }
            #pragma unroll
            for (int nt = 0; nt < 8; nt++) {
                mmah(acc[nt], ph[k2], vh[nt]);
                mmah(acc[nt], pl[k2], vh[nt]);
            }
        }

        MBAR_ARRIVE(mb2 + cb*8);
    }

    // epilogue: write pre-split packed ao [row][kp]
    float inv0 = 1.f / li[0], inv1 = 1.f / li[1];
    #pragma unroll
    for (int nt = 0; nt < 8; nt++) {
        int kp = h*32 + nt*4 + cq;
        size_t r0 = (size_t)(n*SEQ + q0 + rb) * 256 + kp;
        size_t r1 = (size_t)(n*SEQ + q0 + rb + 8) * 256 + kp;
        uint32_t hi, lo;
        split_packh(acc[nt][0]*inv0, acc[nt][1]*inv0, hi, lo);
        g_aoh[r0] = hi; g_aol[r0] = lo;
        split_packh(acc[nt][2]*inv1, acc[nt][3]*inv1, hi, lo);
        g_aoh[r1] = hi; g_aol[r1] = lo;
    }
}

// ============================================================
extern "C" void kernel_launch(void* const* d_in, const int* in_sizes, int n_in,
                              void* d_out, int out_size)
{
    const float* values = (const float*)d_in[0];
    const float* keys   = (const float*)d_in[1];
    const float* query  = (const float*)d_in[2];
    const int*   mask   = (const int*)  d_in[3];
    const float* Wv     = (const float*)d_in[4];
    const float* Wk     = (const float*)d_in[5];
    const float* Wq     = (const float*)d_in[6];
    const float* Wo     = (const float*)d_in[7];
    const float* bo     = (const float*)d_in[8];

    split_w<<<dim3(EMB*EMB/2/256, 4), 256>>>(Wv, Wk, Wq, Wo);
    split_x<<<dim3(NROWS, 3), 256>>>(values, keys, query);

    cudaFuncSetAttribute(proj_kernel, cudaFuncAttributeMaxDynamicSharedMemorySize, GEMM_SMEM);
    proj_kernel<<<dim3(EMB/128, NROWS/128, 3), 256, GEMM_SMEM>>>();

    cudaFuncSetAttribute(flash_kernel, cudaFuncAttributeMaxDynamicSharedMemorySize, FLASH_SMEM);
    flash_kernel<<<dim3(SEQ/BQF, NH), 256, FLASH_SMEM>>>(mask);

    cudaFuncSetAttribute(out_kernel, cudaFuncAttributeMaxDynamicSharedMemorySize, GEMM_SMEM);
    out_kernel<<<dim3(EMB/128, NROWS/128), 256, GEMM_SMEM>>>(bo, (float*)d_out);
}

// round 15
// speedup vs baseline: 1.1351x; 1.1351x over previous
#include <cuda_runtime.h>
#include <cuda_fp16.h>
#include <stdint.h>

#define N_B   8
#define SEQ   2048
#define EMB   512
#define H     8
#define HD    64
#define NROWS (N_B*SEQ)
#define NH    (N_B*H)

// -------- scratch (no cudaMalloc allowed) --------
__device__ uint32_t g_wh[4*256*EMB];
__device__ uint32_t g_qh[(size_t)NH*SEQ*32], g_ql[(size_t)NH*SEQ*32];
__device__ uint32_t g_kh[(size_t)NH*SEQ*32];
__device__ uint32_t g_vh[(size_t)NH*(SEQ/2)*64];
__device__ float g_ao[(size_t)NROWS*EMB];

// ---------------- helpers ----------------
// packed f16x2 convert: d.lo = cvt(x0), d.hi = cvt(x1)
__device__ __forceinline__ uint32_t packh_hi(float x0, float x1) {
    uint32_t r;
    asm("cvt.rn.f16x2.f32 %0, %2, %1;" : "=r"(r) : "f"(x0), "f"(x1));
    return r;
}
__device__ __forceinline__ void split_packh(float x0, float x1, uint32_t &hi, uint32_t &lo) {
    asm("cvt.rn.f16x2.f32 %0, %2, %1;" : "=r"(hi) : "f"(x0), "f"(x1));
    float h0, h1;
    asm("{\n\t.reg .b16 l16, h16;\n\tmov.b32 {l16, h16}, %2;\n\t"
        "cvt.f32.f16 %0, l16;\n\tcvt.f32.f16 %1, h16;\n\t}"
        : "=f"(h0), "=f"(h1) : "r"(hi));
    asm("cvt.rn.f16x2.f32 %0, %2, %1;" : "=r"(lo) : "f"(x0 - h0), "f"(x1 - h1));
}
__device__ __forceinline__ void mmah(float c[4], const uint32_t a[4], const uint32_t b[2]) {
    asm volatile(
      "mma.sync.aligned.m16n8k16.row.col.f32.f16.f16.f32 "
      "{%0,%1,%2,%3},{%4,%5,%6,%7},{%8,%9},{%0,%1,%2,%3};\n"
      : "+f"(c[0]), "+f"(c[1]), "+f"(c[2]), "+f"(c[3])
      : "r"(a[0]), "r"(a[1]), "r"(a[2]), "r"(a[3]), "r"(b[0]), "r"(b[1]));
}
__device__ __forceinline__ void cpa16(void* s, const void* g) {
    uint32_t sa = (uint32_t)__cvta_generic_to_shared(s);
    asm volatile("cp.async.cg.shared.global [%0], [%1], 16;" :: "r"(sa), "l"(g) : "memory");
}
__device__ __forceinline__ float ex2f(float x) {
    float r; asm("ex2.approx.ftz.f32 %0, %1;" : "=f"(r) : "f"(x)); return r;
}
#define CPCOMMIT() asm volatile("cp.async.commit_group;" ::: "memory")
#define CPWAIT(n)  asm volatile("cp.async.wait_group %0;" :: "n"(n) : "memory")
#define CPA_ARRIVE(a) asm volatile("cp.async.mbarrier.arrive.noinc.shared.b64 [%0];" :: "r"(a) : "memory")
#define MBAR_INIT(a, c)   asm volatile("mbarrier.init.shared.b64 [%0], %1;" :: "r"(a), "r"(c) : "memory")
#define MBAR_ARRIVE(a)    asm volatile("mbarrier.arrive.shared.b64 _, [%0];" :: "r"(a) : "memory")
#define MBAR_WAIT(a, par) do { \
    asm volatile("{\n\t.reg .pred P1;\n\tWL%=:\n\t" \
        "mbarrier.try_wait.parity.acquire.cta.shared::cta.b64 P1, [%0], %1, 0x989680;\n\t" \
        "@P1 bra.uni WD%=;\n\tbra.uni WL%=;\n\tWD%=:\n\t}" \
        :: "r"(a), "r"(par) : "memory"); } while (0)

// ============================================================
// Pre-split weights -> fp16 hi pairs packed along k.
// ============================================================
__global__ __launch_bounds__(256) void split_w(
    const float* __restrict__ Wv, const float* __restrict__ Wk,
    const float* __restrict__ Wq, const float* __restrict__ Wo)
{
    const int slot = blockIdx.y;
    const float* src = (slot==0)?Wv:(slot==1)?Wk:(slot==2)?Wq:Wo;
    int i = blockIdx.x * 256 + threadIdx.x;
    int kp = i >> 9, n = i & 511;
    float x0 = src[(2*kp  ) * EMB + n];
    float x1 = src[(2*kp+1) * EMB + n];
    g_wh[(size_t)slot*256*EMB + i] = packh_hi(x0, x1);
}

// ============================================================
// fp16x2 GEMM core: ktile 32, 3-stage ring, one sync/tile.
// A split inline (hi+lo), B hi-only.
// ============================================================
#define AST 36
#define BSTP 136
#define GA (3*128*AST)
#define GB (3*16*BSTP)
#define GEMM_SMEM ((GA + GB) * 4)

__device__ __forceinline__ void gemm_prefetch(
    const float* __restrict__ X, const uint32_t* __restrict__ Wh,
    float* As, uint32_t* Bh, int m0, int n0, int k0, int buf, int tid)
{
    #pragma unroll
    for (int it = 0; it < 4; it++) {
        int f = tid + 256 * it;
        int row = f >> 3, c4 = f & 7;
        cpa16(&As[(buf*128 + row)*AST + c4*4], X + (size_t)(m0+row)*EMB + k0 + c4*4);
    }
    const int kp0 = k0 >> 1;
    #pragma unroll
    for (int it = 0; it < 2; it++) {
        int f = tid + 256 * it;
        int row = f >> 5, c4 = f & 31;
        cpa16(&Bh[(buf*16 + row)*BSTP + c4*4], Wh + (size_t)(kp0+row)*EMB + n0 + c4*4);
    }
}

__device__ __forceinline__ void gemm_core(
    const float* __restrict__ X, const uint32_t* __restrict__ Wh,
    float* sm, float c[2][8][4], int m0, int n0, int tid)
{
    float* As = sm;
    uint32_t* Bh = (uint32_t*)(sm + GA);

    const int lane = tid & 31, w = tid >> 5;
    const int g = lane >> 2, cq = lane & 3;
    const int wm = (w & 3) * 32, wn = (w >> 2) * 64;

    #pragma unroll
    for (int mt = 0; mt < 2; mt++)
        #pragma unroll
        for (int nt = 0; nt < 8; nt++)
            #pragma unroll
            for (int e = 0; e < 4; e++) c[mt][nt][e] = 0.f;

    gemm_prefetch(X, Wh, As, Bh, m0, n0, 0, 0, tid);
    CPCOMMIT();
    gemm_prefetch(X, Wh, As, Bh, m0, n0, 32, 1, tid);
    CPCOMMIT();

    for (int t = 0; t < 16; t++) {
        CPWAIT(1);
        __syncthreads();
        if (t + 2 < 16)
            gemm_prefetch(X, Wh, As, Bh, m0, n0, (t+2)*32, (t+2)%3, tid);
        CPCOMMIT();

        const int cb = t % 3;
        const int ab = cb * 128, bb = cb * 16;
        #pragma unroll
        for (int ks = 0; ks < 2; ks++) {
            uint32_t ah[2][4], al[2][4];
            #pragma unroll
            for (int mt = 0; mt < 2; mt++) {
                int rb = ab + wm + mt*16 + g;
                int kb = ks*16 + 2*cq;
                float2 v0 = *(const float2*)&As[(rb    )*AST + kb    ];
                float2 v1 = *(const float2*)&As[(rb + 8)*AST + kb    ];
                float2 v2 = *(const float2*)&As[(rb    )*AST + kb + 8];
                float2 v3 = *(const float2*)&As[(rb + 8)*AST + kb + 8];
                split_packh(v0.x, v0.y, ah[mt][0], al[mt][0]);
                split_packh(v1.x, v1.y, ah[mt][1], al[mt][1]);
                split_packh(v2.x, v2.y, ah[mt][2], al[mt][2]);
                split_packh(v3.x, v3.y, ah[mt][3], al[mt][3]);
            }
            uint32_t bh[8][2];
            #pragma unroll
            for (int nt = 0; nt < 8; nt++) {
                int nn = wn + nt*8 + g;
                int kp = bb + ks*8 + cq;
                bh[nt][0] = Bh[(kp    )*BSTP + nn];
                bh[nt][1] = Bh[(kp + 4)*BSTP + nn];
            }
            #pragma unroll
            for (int mt = 0; mt < 2; mt++)
                #pragma unroll
                for (int nt = 0; nt < 8; nt++) {
                    mmah(c[mt][nt], ah[mt], bh[nt]);
                    mmah(c[mt][nt], al[mt], bh[nt]);
                }
        }
    }
}

// ============================================================
// Projections. Q: *0.125*log2(e), hi+lo. K: hi. V: hi via shfl.
// ============================================================
__global__ __launch_bounds__(256, 2) void proj_kernel(
    const float* __restrict__ values, const float* __restrict__ keys,
    const float* __restrict__ query)
{
    extern __shared__ float sm[];
    const int which = blockIdx.z;
    const float* X = (which == 0) ? values : (which == 1) ? keys : query;
    const uint32_t* Wh = g_wh + (size_t)which * 256 * EMB;

    const int m0 = blockIdx.y * 128, n0 = blockIdx.x * 128;
    float c[2][8][4];
    gemm_core(X, Wh, sm, c, m0, n0, threadIdx.x);

    const int lane = threadIdx.x & 31, w = threadIdx.x >> 5;
    const int g = lane >> 2, cq = lane & 3;
    const int wm = (w & 3) * 32, wn = (w >> 2) * 64;

    if (which == 2) {
        const float post = 0.125f * 1.44269504f;
        #pragma unroll
        for (int mt = 0; mt < 2; mt++)
            #pragma unroll
            for (int half = 0; half < 2; half++) {
                int row = m0 + wm + mt*16 + g + half*8;
                int n = row >> 11, s = row & 2047;
                #pragma unroll
                for (int nt = 0; nt < 8; nt++) {
                    int col = n0 + wn + nt*8 + 2*cq;
                    int h = col >> 6, d = col & 63;
                    size_t base = ((size_t)(n*H + h)*SEQ + s)*32 + (d >> 1);
                    uint32_t hi, lo;
                    split_packh(c[mt][nt][half*2+0]*post, c[mt][nt][half*2+1]*post, hi, lo);
                    g_qh[base] = hi; g_ql[base] = lo;
                }
            }
    } else if (which == 1) {
        #pragma unroll
        for (int mt = 0; mt < 2; mt++)
            #pragma unroll
            for (int half = 0; half < 2; half++) {
                int row = m0 + wm + mt*16 + g + half*8;
                int n = row >> 11, s = row & 2047;
                #pragma unroll
                for (int nt = 0; nt < 8; nt++) {
                    int col = n0 + wn + nt*8 + 2*cq;
                    int h = col >> 6, d = col & 63;
                    size_t base = ((size_t)(n*H + h)*SEQ + s)*32 + (d >> 1);
                    g_kh[base] = packh_hi(c[mt][nt][half*2+0], c[mt][nt][half*2+1]);
                }
            }
    } else {
        #pragma unroll
        for (int mt = 0; mt < 2; mt++)
            #pragma unroll
            for (int nt = 0; nt < 8; nt++) {
                float p0 = __shfl_xor_sync(0xffffffffu, c[mt][nt][0], 4);
                float p1 = __shfl_xor_sync(0xffffffffu, c[mt][nt][1], 4);
                float p2 = __shfl_xor_sync(0xffffffffu, c[mt][nt][2], 4);
                float p3 = __shfl_xor_sync(0xffffffffu, c[mt][nt][3], 4);
                if ((g & 1) == 0) {
                    int col = n0 + wn + nt*8 + 2*cq;
                    int h = col >> 6, d = col & 63;
                    #pragma unroll
                    for (int half = 0; half < 2; half++) {
                        int row = m0 + wm + mt*16 + g + half*8;
                        int n = row >> 11, s = row & 2047;
                        size_t base = ((size_t)(n*H + h)*(SEQ/2) + (s >> 1))*64 + d;
                        float m0v = c[mt][nt][half*2+0], m1v = c[mt][nt][half*2+1];
                        float q0v = (half == 0) ? p0 : p2;
                        float q1v = (half == 0) ? p1 : p3;
                        g_vh[base    ] = packh_hi(m0v, q0v);
                        g_vh[base + 1] = packh_hi(m1v, q1v);
                    }
                }
            }
    }
}

// ============================================================
// Output GEMM: out = g_ao @ Wo + bo
// ============================================================
__global__ __launch_bounds__(256, 2) void out_kernel(
    const float* __restrict__ bo, float* __restrict__ out)
{
    extern __shared__ float sm[];
    const int m0 = blockIdx.y * 128, n0 = blockIdx.x * 128;
    float c[2][8][4];
    gemm_core(g_ao, g_wh + (size_t)3*256*EMB, sm, c, m0, n0, threadIdx.x);

    const int lane = threadIdx.x & 31, w = threadIdx.x >> 5;
    const int g = lane >> 2, cq = lane & 3;
    const int wm = (w & 3) * 32, wn = (w >> 2) * 64;

    #pragma unroll
    for (int mt = 0; mt < 2; mt++)
        #pragma unroll
        for (int half = 0; half < 2; half++) {
            size_t row = m0 + wm + mt*16 + g + half*8;
            #pragma unroll
            for (int nt = 0; nt < 8; nt++) {
                int col = n0 + wn + nt*8 + 2*cq;
                float2 v = make_float2(c[mt][nt][half*2+0] + bo[col],
                                       c[mt][nt][half*2+1] + bo[col+1]);
                *(float2*)&out[row * EMB + col] = v;
            }
        }
}

// ============================================================
// Flash attention (R12): fp16x2, BQ=128, BKV=32, 4-stage
// mbarrier pipeline, no __syncthreads in loop. K/V hi-only.
// ============================================================
#define BQF 128
#define BKV 32
#define SFL 4
#define KSTP 36
#define VSTP 72
#define NT (SEQ/BKV)
#define FK (SFL*BKV*KSTP)
#define FV (SFL*(BKV/2)*VSTP)
#define FL_MS (FK + FV)
#define FL_MB (FL_MS + SFL*BKV)
#define FLASH_SMEM (FL_MB*4 + 64)

__device__ __forceinline__ void flash_fill(
    const uint32_t* __restrict__ Khg, const uint32_t* __restrict__ Vhg,
    const int* __restrict__ mrow, uint32_t* Kh, uint32_t* Vh,
    int* ms, int k0, int buf, int tid)
{
    int row = tid >> 3, c4 = tid & 7;
    cpa16(&Kh[(buf*BKV+row)*KSTP + c4*4], Khg + (size_t)(k0+row)*32 + c4*4);
    int vr = tid >> 4, vc = tid & 15;
    cpa16(&Vh[(buf*(BKV/2)+vr)*VSTP + vc*4], Vhg + (size_t)(k0/2+vr)*64 + vc*4);
    if (tid < 8) cpa16(&ms[buf*BKV + tid*4], mrow + k0 + tid*4);
}

__global__ __launch_bounds__(256, 2) void flash_kernel(const int* __restrict__ mask)
{
    extern __shared__ uint32_t smu[];
    uint32_t* Kh = smu;
    uint32_t* Vh = Kh + FK;
    int*      ms = (int*)(smu + FL_MS);
    const uint32_t sbF = (uint32_t)__cvta_generic_to_shared(smu);
    const uint32_t mb1 = sbF + FL_MB*4;
    const uint32_t mb2 = sbF + FL_MB*4 + 32;

    const int tid = threadIdx.x;
    const int lane = tid & 31, w = tid >> 5;
    const int g = lane >> 2, cq = lane & 3;
    const int q0 = blockIdx.x * BQF;
    const int nh = blockIdx.y;
    const int n = nh >> 3, h = nh & 7;
    const uint32_t* Qhg = g_qh + (size_t)nh * SEQ * 32;
    const uint32_t* Qlg = g_ql + (size_t)nh * SEQ * 32;
    const uint32_t* Khg = g_kh + (size_t)nh * SEQ * 32;
    const uint32_t* Vhg = g_vh + (size_t)nh * (SEQ/2) * 64;
    const int* mrow = mask + n * SEQ;
    const int rb = w * 16 + g;

    if (tid == 0) {
        #pragma unroll
        for (int s = 0; s < SFL; s++) {
            MBAR_INIT(mb1 + s*8, 256);
            MBAR_INIT(mb2 + s*8, 256);
        }
    }
    __syncthreads();

    flash_fill(Khg, Vhg, mrow, Kh, Vh, ms, 0, 0, tid);
    CPA_ARRIVE(mb1 + 0*8);
    flash_fill(Khg, Vhg, mrow, Kh, Vh, ms, BKV, 1, tid);
    CPA_ARRIVE(mb1 + 1*8);

    uint32_t qh[4][4], ql[4][4];
    {
        const int r0 = q0 + rb, r1 = r0 + 8;
        #pragma unroll
        for (int ks = 0; ks < 4; ks++) {
            int d0 = ks*8 + cq, d1 = ks*8 + 4 + cq;
            qh[ks][0] = Qhg[(size_t)r0*32 + d0];
            qh[ks][1] = Qhg[(size_t)r1*32 + d0];
            qh[ks][2] = Qhg[(size_t)r0*32 + d1];
            qh[ks][3] = Qhg[(size_t)r1*32 + d1];
            ql[ks][0] = Qlg[(size_t)r0*32 + d0];
            ql[ks][1] = Qlg[(size_t)r1*32 + d0];
            ql[ks][2] = Qlg[(size_t)r0*32 + d1];
            ql[ks][3] = Qlg[(size_t)r1*32 + d1];
        }
    }

    float acc[8][4];
    float mi[2] = {-1e30f, -1e30f}, li[2] = {0.f, 0.f};
    #pragma unroll
    for (int nt = 0; nt < 8; nt++)
        #pragma unroll
        for (int e = 0; e < 4; e++) acc[nt][e] = 0.f;

    for (int t = 0; t < NT; t++) {
        const int f = t + 2;
        if (f < NT) {
            const int s = f & 3;
            if (t >= 2) MBAR_WAIT(mb2 + s*8, ((t - 2) >> 2) & 1);
            flash_fill(Khg, Vhg, mrow, Kh, Vh, ms, f*BKV, s, tid);
            CPA_ARRIVE(mb1 + s*8);
        }

        const int cb = t & 3;
        MBAR_WAIT(mb1 + cb*8, (t >> 2) & 1);

        const uint32_t* KhC = Kh + cb * BKV * KSTP;
        const uint32_t* VhC = Vh + cb * (BKV/2) * VSTP;
        const int*      msC = ms + cb * BKV;

        float s[4][4];
        #pragma unroll
        for (int nt = 0; nt < 4; nt++)
            #pragma unroll
            for (int e = 0; e < 4; e++) s[nt][e] = 0.f;

        #pragma unroll
        for (int ks = 0; ks < 4; ks++) {
            int d0 = ks*8 + cq, d1 = ks*8 + 4 + cq;
            uint32_t bh[4][2];
            #pragma unroll
            for (int nt = 0; nt < 4; nt++) {
                int nn = nt*8 + g;
                bh[nt][0] = KhC[nn*KSTP + d0];
                bh[nt][1] = KhC[nn*KSTP + d1];
            }
            #pragma unroll
            for (int nt = 0; nt < 4; nt++) {
                mmah(s[nt], qh[ks], bh[nt]);
                mmah(s[nt], ql[ks], bh[nt]);
            }
        }

        float mx0 = -1e30f, mx1 = -1e30f;
        #pragma unroll
        for (int nt = 0; nt < 4; nt++) {
            #pragma unroll
            for (int j = 0; j < 2; j++) {
                int mv = msC[nt*8 + 2*cq + j];
                float v0 = mv ? s[nt][j]   : -1e30f;
                float v1 = mv ? s[nt][2+j] : -1e30f;
                s[nt][j] = v0; s[nt][2+j] = v1;
                mx0 = fmaxf(mx0, v0); mx1 = fmaxf(mx1, v1);
            }
        }
        mx0 = fmaxf(mx0, __shfl_xor_sync(0xffffffffu, mx0, 1));
        mx0 = fmaxf(mx0, __shfl_xor_sync(0xffffffffu, mx0, 2));
        mx1 = fmaxf(mx1, __shfl_xor_sync(0xffffffffu, mx1, 1));
        mx1 = fmaxf(mx1, __shfl_xor_sync(0xffffffffu, mx1, 2));

        float mn0 = fmaxf(mi[0], mx0), mn1 = fmaxf(mi[1], mx1);
        float cr0 = ex2f(mi[0] - mn0), cr1 = ex2f(mi[1] - mn1);
        float sum0 = 0.f, sum1 = 0.f;
        #pragma unroll
        for (int nt = 0; nt < 4; nt++) {
            s[nt][0] = ex2f(s[nt][0] - mn0);
            s[nt][1] = ex2f(s[nt][1] - mn0);
            s[nt][2] = ex2f(s[nt][2] - mn1);
            s[nt][3] = ex2f(s[nt][3] - mn1);
            sum0 += s[nt][0] + s[nt][1];
            sum1 += s[nt][2] + s[nt][3];
        }
        sum0 += __shfl_xor_sync(0xffffffffu, sum0, 1);
        sum0 += __shfl_xor_sync(0xffffffffu, sum0, 2);
        sum1 += __shfl_xor_sync(0xffffffffu, sum1, 1);
        sum1 += __shfl_xor_sync(0xffffffffu, sum1, 2);
        li[0] = li[0] * cr0 + sum0; mi[0] = mn0;
        li[1] = li[1] * cr1 + sum1; mi[1] = mn1;
        #pragma unroll
        for (int nt = 0; nt < 8; nt++) {
            acc[nt][0] *= cr0; acc[nt][1] *= cr0;
            acc[nt][2] *= cr1; acc[nt][3] *= cr1;
        }

        uint32_t ph[2][4], pl[2][4];
        #pragma unroll
        for (int k2 = 0; k2 < 2; k2++) {
            split_packh(s[2*k2  ][0], s[2*k2  ][1], ph[k2][0], pl[k2][0]);
            split_packh(s[2*k2  ][2], s[2*k2  ][3], ph[k2][1], pl[k2][1]);
            split_packh(s[2*k2+1][0], s[2*k2+1][1], ph[k2][2], pl[k2][2]);
            split_packh(s[2*k2+1][2], s[2*k2+1][3], ph[k2][3], pl[k2][3]);
        }

        #pragma unroll
        for (int k2 = 0; k2 < 2; k2++) {
            int sp0 = k2*8 + cq, sp1 = k2*8 + 4 + cq;
            uint32_t vh[8][2];
            #pragma unroll
            for (int nt = 0; nt < 8; nt++) {
                int dd = nt*8 + g;
                vh[nt][0] = VhC[sp0*VSTP + dd];
                vh[nt][1] = VhC[sp1*VSTP + dd];
            }
            #pragma unroll
            for (int nt = 0; nt < 8; nt++) {
                mmah(acc[nt], ph[k2], vh[nt]);
                mmah(acc[nt], pl[k2], vh[nt]);
            }
        }

        MBAR_ARRIVE(mb2 + cb*8);
    }

    float inv0 = 1.f / li[0], inv1 = 1.f / li[1];
    #pragma unroll
    for (int nt = 0; nt < 8; nt++) {
        int col = h * 64 + nt * 8 + 2 * cq;
        size_t r0 = (size_t)(n * SEQ + q0 + rb) * EMB + col;
        size_t r1 = (size_t)(n * SEQ + q0 + rb + 8) * EMB + col;
        *(float2*)&g_ao[r0] = make_float2(acc[nt][0]*inv0, acc[nt][1]*inv0);
        *(float2*)&g_ao[r1] = make_float2(acc[nt][2]*inv1, acc[nt][3]*inv1);
    }
}

// ============================================================
extern "C" void kernel_launch(void* const* d_in, const int* in_sizes, int n_in,
                              void* d_out, int out_size)
{
    const float* values = (const float*)d_in[0];
    const float* keys   = (const float*)d_in[1];
    const float* query  = (const float*)d_in[2];
    const int*   mask   = (const int*)  d_in[3];
    const float* Wv     = (const float*)d_in[4];
    const float* Wk     = (const float*)d_in[5];
    const float* Wq     = (const float*)d_in[6];
    const float* Wo     = (const float*)d_in[7];
    const float* bo     = (const float*)d_in[8];

    split_w<<<dim3(EMB*EMB/2/256, 4), 256>>>(Wv, Wk, Wq, Wo);

    cudaFuncSetAttribute(proj_kernel, cudaFuncAttributeMaxDynamicSharedMemorySize, GEMM_SMEM);
    proj_kernel<<<dim3(EMB/128, NROWS/128, 3), 256, GEMM_SMEM>>>(values, keys, query);

    cudaFuncSetAttribute(flash_kernel, cudaFuncAttributeMaxDynamicSharedMemorySize, FLASH_SMEM);
    flash_kernel<<<dim3(SEQ/BQF, NH), 256, FLASH_SMEM>>>(mask);

    cudaFuncSetAttribute(out_kernel, cudaFuncAttributeMaxDynamicSharedMemorySize, GEMM_SMEM);
    out_kernel<<<dim3(EMB/128, NROWS/128), 256, GEMM_SMEM>>>(bo, (float*)d_out);
}

// round 16
// speedup vs baseline: 1.1652x; 1.0265x over previous
#include <cuda_runtime.h>
#include <cuda_fp16.h>
#include <stdint.h>

#define N_B   8
#define SEQ   2048
#define EMB   512
#define H     8
#define HD    64
#define NROWS (N_B*SEQ)
#define NH    (N_B*H)

// -------- scratch (no cudaMalloc allowed) --------
__device__ uint32_t g_wh[4*256*EMB];
__device__ uint32_t g_qh[(size_t)NH*SEQ*32], g_ql[(size_t)NH*SEQ*32];
__device__ uint32_t g_kh[(size_t)NH*SEQ*32];
__device__ uint32_t g_vh[(size_t)NH*(SEQ/2)*64];
__device__ float g_ao[(size_t)NROWS*EMB];

// ---------------- helpers ----------------
// packed f16x2 convert: d.lo = cvt(x0), d.hi = cvt(x1)
__device__ __forceinline__ uint32_t packh_hi(float x0, float x1) {
    uint32_t r;
    asm("cvt.rn.f16x2.f32 %0, %2, %1;" : "=r"(r) : "f"(x0), "f"(x1));
    return r;
}
__device__ __forceinline__ void split_packh(float x0, float x1, uint32_t &hi, uint32_t &lo) {
    asm("cvt.rn.f16x2.f32 %0, %2, %1;" : "=r"(hi) : "f"(x0), "f"(x1));
    float h0, h1;
    asm("{\n\t.reg .b16 l16, h16;\n\tmov.b32 {l16, h16}, %2;\n\t"
        "cvt.f32.f16 %0, l16;\n\tcvt.f32.f16 %1, h16;\n\t}"
        : "=f"(h0), "=f"(h1) : "r"(hi));
    asm("cvt.rn.f16x2.f32 %0, %2, %1;" : "=r"(lo) : "f"(x0 - h0), "f"(x1 - h1));
}
__device__ __forceinline__ void mmah(float c[4], const uint32_t a[4], const uint32_t b[2]) {
    asm volatile(
      "mma.sync.aligned.m16n8k16.row.col.f32.f16.f16.f32 "
      "{%0,%1,%2,%3},{%4,%5,%6,%7},{%8,%9},{%0,%1,%2,%3};\n"
      : "+f"(c[0]), "+f"(c[1]), "+f"(c[2]), "+f"(c[3])
      : "r"(a[0]), "r"(a[1]), "r"(a[2]), "r"(a[3]), "r"(b[0]), "r"(b[1]));
}
__device__ __forceinline__ void cpa16(void* s, const void* g) {
    uint32_t sa = (uint32_t)__cvta_generic_to_shared(s);
    asm volatile("cp.async.cg.shared.global [%0], [%1], 16;" :: "r"(sa), "l"(g) : "memory");
}
__device__ __forceinline__ float ex2f(float x) {
    float r; asm("ex2.approx.ftz.f32 %0, %1;" : "=f"(r) : "f"(x)); return r;
}
#define CPCOMMIT() asm volatile("cp.async.commit_group;" ::: "memory")
#define CPWAIT(n)  asm volatile("cp.async.wait_group %0;" :: "n"(n) : "memory")
#define CPA_ARRIVE(a) asm volatile("cp.async.mbarrier.arrive.noinc.shared.b64 [%0];" :: "r"(a) : "memory")
#define MBAR_INIT(a, c)   asm volatile("mbarrier.init.shared.b64 [%0], %1;" :: "r"(a), "r"(c) : "memory")
#define MBAR_ARRIVE(a)    asm volatile("mbarrier.arrive.shared.b64 _, [%0];" :: "r"(a) : "memory")
#define MBAR_WAIT(a, par) do { \
    asm volatile("{\n\t.reg .pred P1;\n\tWL%=:\n\t" \
        "mbarrier.try_wait.parity.acquire.cta.shared::cta.b64 P1, [%0], %1, 0x989680;\n\t" \
        "@P1 bra.uni WD%=;\n\tbra.uni WL%=;\n\tWD%=:\n\t}" \
        :: "r"(a), "r"(par) : "memory"); } while (0)

// ============================================================
// Pre-split weights -> fp16 hi pairs packed along k.
// ============================================================
__global__ __launch_bounds__(256) void split_w(
    const float* __restrict__ Wv, const float* __restrict__ Wk,
    const float* __restrict__ Wq, const float* __restrict__ Wo)
{
    const int slot = blockIdx.y;
    const float* src = (slot==0)?Wv:(slot==1)?Wk:(slot==2)?Wq:Wo;
    int i = blockIdx.x * 256 + threadIdx.x;
    int kp = i >> 9, n = i & 511;
    float x0 = src[(2*kp  ) * EMB + n];
    float x1 = src[(2*kp+1) * EMB + n];
    g_wh[(size_t)slot*256*EMB + i] = packh_hi(x0, x1);
}

// ============================================================
// fp16x2 GEMM core: ktile 32, 3-stage ring, one sync/tile.
// A stride 40 -> conflict-free LDS.64 fragment loads.
// ============================================================
#define AST 40
#define BSTP 136
#define GA (3*128*AST)
#define GB (3*16*BSTP)
#define GEMM_SMEM ((GA + GB) * 4)

__device__ __forceinline__ void gemm_prefetch(
    const float* __restrict__ X, const uint32_t* __restrict__ Wh,
    float* As, uint32_t* Bh, int m0, int n0, int k0, int buf, int tid)
{
    #pragma unroll
    for (int it = 0; it < 4; it++) {
        int f = tid + 256 * it;
        int row = f >> 3, c4 = f & 7;
        cpa16(&As[(buf*128 + row)*AST + c4*4], X + (size_t)(m0+row)*EMB + k0 + c4*4);
    }
    const int kp0 = k0 >> 1;
    #pragma unroll
    for (int it = 0; it < 2; it++) {
        int f = tid + 256 * it;
        int row = f >> 5, c4 = f & 31;
        cpa16(&Bh[(buf*16 + row)*BSTP + c4*4], Wh + (size_t)(kp0+row)*EMB + n0 + c4*4);
    }
}

__device__ __forceinline__ void gemm_core(
    const float* __restrict__ X, const uint32_t* __restrict__ Wh,
    float* sm, float c[2][8][4], int m0, int n0, int tid)
{
    float* As = sm;
    uint32_t* Bh = (uint32_t*)(sm + GA);

    const int lane = tid & 31, w = tid >> 5;
    const int g = lane >> 2, cq = lane & 3;
    const int wm = (w & 3) * 32, wn = (w >> 2) * 64;

    #pragma unroll
    for (int mt = 0; mt < 2; mt++)
        #pragma unroll
        for (int nt = 0; nt < 8; nt++)
            #pragma unroll
            for (int e = 0; e < 4; e++) c[mt][nt][e] = 0.f;

    gemm_prefetch(X, Wh, As, Bh, m0, n0, 0, 0, tid);
    CPCOMMIT();
    gemm_prefetch(X, Wh, As, Bh, m0, n0, 32, 1, tid);
    CPCOMMIT();

    for (int t = 0; t < 16; t++) {
        CPWAIT(1);
        __syncthreads();
        if (t + 2 < 16)
            gemm_prefetch(X, Wh, As, Bh, m0, n0, (t+2)*32, (t+2)%3, tid);
        CPCOMMIT();

        const int cb = t % 3;
        const int ab = cb * 128, bb = cb * 16;
        #pragma unroll
        for (int ks = 0; ks < 2; ks++) {
            uint32_t ah[2][4], al[2][4];
            #pragma unroll
            for (int mt = 0; mt < 2; mt++) {
                int rb = ab + wm + mt*16 + g;
                int kb = ks*16 + 2*cq;
                float2 v0 = *(const float2*)&As[(rb    )*AST + kb    ];
                float2 v1 = *(const float2*)&As[(rb + 8)*AST + kb    ];
                float2 v2 = *(const float2*)&As[(rb    )*AST + kb + 8];
                float2 v3 = *(const float2*)&As[(rb + 8)*AST + kb + 8];
                split_packh(v0.x, v0.y, ah[mt][0], al[mt][0]);
                split_packh(v1.x, v1.y, ah[mt][1], al[mt][1]);
                split_packh(v2.x, v2.y, ah[mt][2], al[mt][2]);
                split_packh(v3.x, v3.y, ah[mt][3], al[mt][3]);
            }
            uint32_t bh[8][2];
            #pragma unroll
            for (int nt = 0; nt < 8; nt++) {
                int nn = wn + nt*8 + g;
                int kp = bb + ks*8 + cq;
                bh[nt][0] = Bh[(kp    )*BSTP + nn];
                bh[nt][1] = Bh[(kp + 4)*BSTP + nn];
            }
            #pragma unroll
            for (int mt = 0; mt < 2; mt++)
                #pragma unroll
                for (int nt = 0; nt < 8; nt++) {
                    mmah(c[mt][nt], ah[mt], bh[nt]);
                    mmah(c[mt][nt], al[mt], bh[nt]);
                }
        }
    }
}

// ============================================================
// Projections. Q: *0.125*log2(e), hi+lo. K: hi. V: hi via shfl.
// ============================================================
__global__ __launch_bounds__(256, 2) void proj_kernel(
    const float* __restrict__ values, const float* __restrict__ keys,
    const float* __restrict__ query)
{
    extern __shared__ float sm[];
    const int which = blockIdx.z;
    const float* X = (which == 0) ? values : (which == 1) ? keys : query;
    const uint32_t* Wh = g_wh + (size_t)which * 256 * EMB;

    const int m0 = blockIdx.y * 128, n0 = blockIdx.x * 128;
    float c[2][8][4];
    gemm_core(X, Wh, sm, c, m0, n0, threadIdx.x);

    const int lane = threadIdx.x & 31, w = threadIdx.x >> 5;
    const int g = lane >> 2, cq = lane & 3;
    const int wm = (w & 3) * 32, wn = (w >> 2) * 64;

    if (which == 2) {
        const float post = 0.125f * 1.44269504f;
        #pragma unroll
        for (int mt = 0; mt < 2; mt++)
            #pragma unroll
            for (int half = 0; half < 2; half++) {
                int row = m0 + wm + mt*16 + g + half*8;
                int n = row >> 11, s = row & 2047;
                #pragma unroll
                for (int nt = 0; nt < 8; nt++) {
                    int col = n0 + wn + nt*8 + 2*cq;
                    int h = col >> 6, d = col & 63;
                    size_t base = ((size_t)(n*H + h)*SEQ + s)*32 + (d >> 1);
                    uint32_t hi, lo;
                    split_packh(c[mt][nt][half*2+0]*post, c[mt][nt][half*2+1]*post, hi, lo);
                    g_qh[base] = hi; g_ql[base] = lo;
                }
            }
    } else if (which == 1) {
        #pragma unroll
        for (int mt = 0; mt < 2; mt++)
            #pragma unroll
            for (int half = 0; half < 2; half++) {
                int row = m0 + wm + mt*16 + g + half*8;
                int n = row >> 11, s = row & 2047;
                #pragma unroll
                for (int nt = 0; nt < 8; nt++) {
                    int col = n0 + wn + nt*8 + 2*cq;
                    int h = col >> 6, d = col & 63;
                    size_t base = ((size_t)(n*H + h)*SEQ + s)*32 + (d >> 1);
                    g_kh[base] = packh_hi(c[mt][nt][half*2+0], c[mt][nt][half*2+1]);
                }
            }
    } else {
        #pragma unroll
        for (int mt = 0; mt < 2; mt++)
            #pragma unroll
            for (int nt = 0; nt < 8; nt++) {
                float p0 = __shfl_xor_sync(0xffffffffu, c[mt][nt][0], 4);
                float p1 = __shfl_xor_sync(0xffffffffu, c[mt][nt][1], 4);
                float p2 = __shfl_xor_sync(0xffffffffu, c[mt][nt][2], 4);
                float p3 = __shfl_xor_sync(0xffffffffu, c[mt][nt][3], 4);
                if ((g & 1) == 0) {
                    int col = n0 + wn + nt*8 + 2*cq;
                    int h = col >> 6, d = col & 63;
                    #pragma unroll
                    for (int half = 0; half < 2; half++) {
                        int row = m0 + wm + mt*16 + g + half*8;
                        int n = row >> 11, s = row & 2047;
                        size_t base = ((size_t)(n*H + h)*(SEQ/2) + (s >> 1))*64 + d;
                        float m0v = c[mt][nt][half*2+0], m1v = c[mt][nt][half*2+1];
                        float q0v = (half == 0) ? p0 : p2;
                        float q1v = (half == 0) ? p1 : p3;
                        g_vh[base    ] = packh_hi(m0v, q0v);
                        g_vh[base + 1] = packh_hi(m1v, q1v);
                    }
                }
            }
    }
}

// ============================================================
// Output GEMM: out = g_ao @ Wo + bo
// ============================================================
__global__ __launch_bounds__(256, 2) void out_kernel(
    const float* __restrict__ bo, float* __restrict__ out)
{
    extern __shared__ float sm[];
    const int m0 = blockIdx.y * 128, n0 = blockIdx.x * 128;
    float c[2][8][4];
    gemm_core(g_ao, g_wh + (size_t)3*256*EMB, sm, c, m0, n0, threadIdx.x);

    const int lane = threadIdx.x & 31, w = threadIdx.x >> 5;
    const int g = lane >> 2, cq = lane & 3;
    const int wm = (w & 3) * 32, wn = (w >> 2) * 64;

    #pragma unroll
    for (int mt = 0; mt < 2; mt++)
        #pragma unroll
        for (int half = 0; half < 2; half++) {
            size_t row = m0 + wm + mt*16 + g + half*8;
            #pragma unroll
            for (int nt = 0; nt < 8; nt++) {
                int col = n0 + wn + nt*8 + 2*cq;
                float2 v = make_float2(c[mt][nt][half*2+0] + bo[col],
                                       c[mt][nt][half*2+1] + bo[col+1]);
                *(float2*)&out[row * EMB + col] = v;
            }
        }
}

// ============================================================
// Flash attention (R12/R15): fp16x2, BQ=128, BKV=32, 4-stage
// mbarrier pipeline, no __syncthreads in loop. K/V hi-only.
// ============================================================
#define BQF 128
#define BKV 32
#define SFL 4
#define KSTP 36
#define VSTP 72
#define NT (SEQ/BKV)
#define FK (SFL*BKV*KSTP)
#define FV (SFL*(BKV/2)*VSTP)
#define FL_MS (FK + FV)
#define FL_MB (FL_MS + SFL*BKV)
#define FLASH_SMEM (FL_MB*4 + 64)

__device__ __forceinline__ void flash_fill(
    const uint32_t* __restrict__ Khg, const uint32_t* __restrict__ Vhg,
    const int* __restrict__ mrow, uint32_t* Kh, uint32_t* Vh,
    int* ms, int k0, int buf, int tid)
{
    int row = tid >> 3, c4 = tid & 7;
    cpa16(&Kh[(buf*BKV+row)*KSTP + c4*4], Khg + (size_t)(k0+row)*32 + c4*4);
    int vr = tid >> 4, vc = tid & 15;
    cpa16(&Vh[(buf*(BKV/2)+vr)*VSTP + vc*4], Vhg + (size_t)(k0/2+vr)*64 + vc*4);
    if (tid < 8) cpa16(&ms[buf*BKV + tid*4], mrow + k0 + tid*4);
}

__global__ __launch_bounds__(256, 2) void flash_kernel(const int* __restrict__ mask)
{
    extern __shared__ uint32_t smu[];
    uint32_t* Kh = smu;
    uint32_t* Vh = Kh + FK;
    int*      ms = (int*)(smu + FL_MS);
    const uint32_t sbF = (uint32_t)__cvta_generic_to_shared(smu);
    const uint32_t mb1 = sbF + FL_MB*4;
    const uint32_t mb2 = sbF + FL_MB*4 + 32;

    const int tid = threadIdx.x;
    const int lane = tid & 31, w = tid >> 5;
    const int g = lane >> 2, cq = lane & 3;
    const int q0 = blockIdx.x * BQF;
    const int nh = blockIdx.y;
    const int n = nh >> 3, h = nh & 7;
    const uint32_t* Qhg = g_qh + (size_t)nh * SEQ * 32;
    const uint32_t* Qlg = g_ql + (size_t)nh * SEQ * 32;
    const uint32_t* Khg = g_kh + (size_t)nh * SEQ * 32;
    const uint32_t* Vhg = g_vh + (size_t)nh * (SEQ/2) * 64;
    const int* mrow = mask + n * SEQ;
    const int rb = w * 16 + g;

    if (tid == 0) {
        #pragma unroll
        for (int s = 0; s < SFL; s++) {
            MBAR_INIT(mb1 + s*8, 256);
            MBAR_INIT(mb2 + s*8, 256);
        }
    }
    __syncthreads();

    flash_fill(Khg, Vhg, mrow, Kh, Vh, ms, 0, 0, tid);
    CPA_ARRIVE(mb1 + 0*8);
    flash_fill(Khg, Vhg, mrow, Kh, Vh, ms, BKV, 1, tid);
    CPA_ARRIVE(mb1 + 1*8);

    uint32_t qh[4][4], ql[4][4];
    {
        const int r0 = q0 + rb, r1 = r0 + 8;
        #pragma unroll
        for (int ks = 0; ks < 4; ks++) {
            int d0 = ks*8 + cq, d1 = ks*8 + 4 + cq;
            qh[ks][0] = Qhg[(size_t)r0*32 + d0];
            qh[ks][1] = Qhg[(size_t)r1*32 + d0];
            qh[ks][2] = Qhg[(size_t)r0*32 + d1];
            qh[ks][3] = Qhg[(size_t)r1*32 + d1];
            ql[ks][0] = Qlg[(size_t)r0*32 + d0];
            ql[ks][1] = Qlg[(size_t)r1*32 + d0];
            ql[ks][2] = Qlg[(size_t)r0*32 + d1];
            ql[ks][3] = Qlg[(size_t)r1*32 + d1];
        }
    }

    float acc[8][4];
    float mi[2] = {-1e30f, -1e30f}, li[2] = {0.f, 0.f};
    #pragma unroll
    for (int nt = 0; nt < 8; nt++)
        #pragma unroll
        for (int e = 0; e < 4; e++) acc[nt][e] = 0.f;

    for (int t = 0; t < NT; t++) {
        const int f = t + 2;
        if (f < NT) {
            const int s = f & 3;
            if (t >= 2) MBAR_WAIT(mb2 + s*8, ((t - 2) >> 2) & 1);
            flash_fill(Khg, Vhg, mrow, Kh, Vh, ms, f*BKV, s, tid);
            CPA_ARRIVE(mb1 + s*8);
        }

        const int cb = t & 3;
        MBAR_WAIT(mb1 + cb*8, (t >> 2) & 1);

        const uint32_t* KhC = Kh + cb * BKV * KSTP;
        const uint32_t* VhC = Vh + cb * (BKV/2) * VSTP;
        const int*      msC = ms + cb * BKV;

        float s[4][4];
        #pragma unroll
        for (int nt = 0; nt < 4; nt++)
            #pragma unroll
            for (int e = 0; e < 4; e++) s[nt][e] = 0.f;

        #pragma unroll
        for (int ks = 0; ks < 4; ks++) {
            int d0 = ks*8 + cq, d1 = ks*8 + 4 + cq;
            uint32_t bh[4][2];
            #pragma unroll
            for (int nt = 0; nt < 4; nt++) {
                int nn = nt*8 + g;
                bh[nt][0] = KhC[nn*KSTP + d0];
                bh[nt][1] = KhC[nn*KSTP + d1];
            }
            #pragma unroll
            for (int nt = 0; nt < 4; nt++) {
                mmah(s[nt], qh[ks], bh[nt]);
                mmah(s[nt], ql[ks], bh[nt]);
            }
        }

        float mx0 = -1e30f, mx1 = -1e30f;
        #pragma unroll
        for (int nt = 0; nt < 4; nt++) {
            #pragma unroll
            for (int j = 0; j < 2; j++) {
                int mv = msC[nt*8 + 2*cq + j];
                float v0 = mv ? s[nt][j]   : -1e30f;
                float v1 = mv ? s[nt][2+j] : -1e30f;
                s[nt][j] = v0; s[nt][2+j] = v1;
                mx0 = fmaxf(mx0, v0); mx1 = fmaxf(mx1, v1);
            }
        }
        mx0 = fmaxf(mx0, __shfl_xor_sync(0xffffffffu, mx0, 1));
        mx0 = fmaxf(mx0, __shfl_xor_sync(0xffffffffu, mx0, 2));
        mx1 = fmaxf(mx1, __shfl_xor_sync(0xffffffffu, mx1, 1));
        mx1 = fmaxf(mx1, __shfl_xor_sync(0xffffffffu, mx1, 2));

        float mn0 = fmaxf(mi[0], mx0), mn1 = fmaxf(mi[1], mx1);
        float cr0 = ex2f(mi[0] - mn0), cr1 = ex2f(mi[1] - mn1);
        float sum0 = 0.f, sum1 = 0.f;
        #pragma unroll
        for (int nt = 0; nt < 4; nt++) {
            s[nt][0] = ex2f(s[nt][0] - mn0);
            s[nt][1] = ex2f(s[nt][1] - mn0);
            s[nt][2] = ex2f(s[nt][2] - mn1);
            s[nt][3] = ex2f(s[nt][3] - mn1);
            sum0 += s[nt][0] + s[nt][1];
            sum1 += s[nt][2] + s[nt][3];
        }
        sum0 += __shfl_xor_sync(0xffffffffu, sum0, 1);
        sum0 += __shfl_xor_sync(0xffffffffu, sum0, 2);
        sum1 += __shfl_xor_sync(0xffffffffu, sum1, 1);
        sum1 += __shfl_xor_sync(0xffffffffu, sum1, 2);
        li[0] = li[0] * cr0 + sum0; mi[0] = mn0;
        li[1] = li[1] * cr1 + sum1; mi[1] = mn1;
        #pragma unroll
        for (int nt = 0; nt < 8; nt++) {
            acc[nt][0] *= cr0; acc[nt][1] *= cr0;
            acc[nt][2] *= cr1; acc[nt][3] *= cr1;
        }

        uint32_t ph[2][4], pl[2][4];
        #pragma unroll
        for (int k2 = 0; k2 < 2; k2++) {
            split_packh(s[2*k2  ][0], s[2*k2  ][1], ph[k2][0], pl[k2][0]);
            split_packh(s[2*k2  ][2], s[2*k2  ][3], ph[k2][1], pl[k2][1]);
            split_packh(s[2*k2+1][0], s[2*k2+1][1], ph[k2][2], pl[k2][2]);
            split_packh(s[2*k2+1][2], s[2*k2+1][3], ph[k2][3], pl[k2][3]);
        }

        #pragma unroll
        for (int k2 = 0; k2 < 2; k2++) {
            int sp0 = k2*8 + cq, sp1 = k2*8 + 4 + cq;
            uint32_t vh[8][2];
            #pragma unroll
            for (int nt = 0; nt < 8; nt++) {
                int dd = nt*8 + g;
                vh[nt][0] = VhC[sp0*VSTP + dd];
                vh[nt][1] = VhC[sp1*VSTP + dd];
            }
            #pragma unroll
            for (int nt = 0; nt < 8; nt++) {
                mmah(acc[nt], ph[k2], vh[nt]);
                mmah(acc[nt], pl[k2], vh[nt]);
            }
        }

        MBAR_ARRIVE(mb2 + cb*8);
    }

    float inv0 = 1.f / li[0], inv1 = 1.f / li[1];
    #pragma unroll
    for (int nt = 0; nt < 8; nt++) {
        int col = h * 64 + nt * 8 + 2 * cq;
        size_t r0 = (size_t)(n * SEQ + q0 + rb) * EMB + col;
        size_t r1 = (size_t)(n * SEQ + q0 + rb + 8) * EMB + col;
        *(float2*)&g_ao[r0] = make_float2(acc[nt][0]*inv0, acc[nt][1]*inv0);
        *(float2*)&g_ao[r1] = make_float2(acc[nt][2]*inv1, acc[nt][3]*inv1);
    }
}

// ============================================================
extern "C" void kernel_launch(void* const* d_in, const int* in_sizes, int n_in,
                              void* d_out, int out_size)
{
    const float* values = (const float*)d_in[0];
    const float* keys   = (const float*)d_in[1];
    const float* query  = (const float*)d_in[2];
    const int*   mask   = (const int*)  d_in[3];
    const float* Wv     = (const float*)d_in[4];
    const float* Wk     = (const float*)d_in[5];
    const float* Wq     = (const float*)d_in[6];
    const float* Wo     = (const float*)d_in[7];
    const float* bo     = (const float*)d_in[8];

    split_w<<<dim3(EMB*EMB/2/256, 4), 256>>>(Wv, Wk, Wq, Wo);

    cudaFuncSetAttribute(proj_kernel, cudaFuncAttributeMaxDynamicSharedMemorySize, GEMM_SMEM);
    proj_kernel<<<dim3(EMB/128, NROWS/128, 3), 256, GEMM_SMEM>>>(values, keys, query);

    cudaFuncSetAttribute(flash_kernel, cudaFuncAttributeMaxDynamicSharedMemorySize, FLASH_SMEM);
    flash_kernel<<<dim3(SEQ/BQF, NH), 256, FLASH_SMEM>>>(mask);

    cudaFuncSetAttribute(out_kernel, cudaFuncAttributeMaxDynamicSharedMemorySize, GEMM_SMEM);
    out_kernel<<<dim3(EMB/128, NROWS/128), 256, GEMM_SMEM>>>(bo, (float*)d_out);
}

// round 17
// speedup vs baseline: 1.1813x; 1.0138x over previous
#include <cuda_runtime.h>
#include <cuda_fp16.h>
#include <stdint.h>

#define N_B   8
#define SEQ   2048
#define EMB   512
#define H     8
#define HD    64
#define NROWS (N_B*SEQ)
#define NH    (N_B*H)

// pair permutation within groups of 8 k-pairs: (x, x+4) become adjacent
__device__ __forceinline__ int reord(int dp) {
    return (dp & ~7) | ((dp & 3) << 1) | ((dp >> 2) & 1);
}

// -------- scratch (no cudaMalloc allowed) --------
// W: [slot][g8][pr<4][n<512][e<2]  (pair-packed along k)
__device__ uint32_t g_wh[4*256*EMB];
// q,k: [nh][s][dp'] with dp' = reord(dp)
__device__ uint32_t g_qh[(size_t)NH*SEQ*32], g_ql[(size_t)NH*SEQ*32];
__device__ uint32_t g_kh[(size_t)NH*SEQ*32];
// v: [nh][sg][pr<4][d<64][e<2]  (s-pairs pair-packed)
__device__ uint32_t g_vh[(size_t)NH*(SEQ/2)*64];
__device__ float g_ao[(size_t)NROWS*EMB];

// ---------------- helpers ----------------
__device__ __forceinline__ uint32_t packh_hi(float x0, float x1) {
    uint32_t r;
    asm("cvt.rn.f16x2.f32 %0, %2, %1;" : "=r"(r) : "f"(x0), "f"(x1));
    return r;
}
__device__ __forceinline__ void split_packh(float x0, float x1, uint32_t &hi, uint32_t &lo) {
    asm("cvt.rn.f16x2.f32 %0, %2, %1;" : "=r"(hi) : "f"(x0), "f"(x1));
    float h0, h1;
    asm("{\n\t.reg .b16 l16, h16;\n\tmov.b32 {l16, h16}, %2;\n\t"
        "cvt.f32.f16 %0, l16;\n\tcvt.f32.f16 %1, h16;\n\t}"
        : "=f"(h0), "=f"(h1) : "r"(hi));
    asm("cvt.rn.f16x2.f32 %0, %2, %1;" : "=r"(lo) : "f"(x0 - h0), "f"(x1 - h1));
}
__device__ __forceinline__ void mmah(float c[4], const uint32_t a[4], const uint32_t b[2]) {
    asm volatile(
      "mma.sync.aligned.m16n8k16.row.col.f32.f16.f16.f32 "
      "{%0,%1,%2,%3},{%4,%5,%6,%7},{%8,%9},{%0,%1,%2,%3};\n"
      : "+f"(c[0]), "+f"(c[1]), "+f"(c[2]), "+f"(c[3])
      : "r"(a[0]), "r"(a[1]), "r"(a[2]), "r"(a[3]), "r"(b[0]), "r"(b[1]));
}
__device__ __forceinline__ void cpa16(void* s, const void* g) {
    uint32_t sa = (uint32_t)__cvta_generic_to_shared(s);
    asm volatile("cp.async.cg.shared.global [%0], [%1], 16;" :: "r"(sa), "l"(g) : "memory");
}
__device__ __forceinline__ float ex2f(float x) {
    float r; asm("ex2.approx.ftz.f32 %0, %1;" : "=f"(r) : "f"(x)); return r;
}
#define CPCOMMIT() asm volatile("cp.async.commit_group;" ::: "memory")
#define CPWAIT(n)  asm volatile("cp.async.wait_group %0;" :: "n"(n) : "memory")
#define CPA_ARRIVE(a) asm volatile("cp.async.mbarrier.arrive.noinc.shared.b64 [%0];" :: "r"(a) : "memory")
#define MBAR_INIT(a, c)   asm volatile("mbarrier.init.shared.b64 [%0], %1;" :: "r"(a), "r"(c) : "memory")
#define MBAR_ARRIVE(a)    asm volatile("mbarrier.arrive.shared.b64 _, [%0];" :: "r"(a) : "memory")
#define MBAR_WAIT(a, par) do { \
    asm volatile("{\n\t.reg .pred P1;\n\tWL%=:\n\t" \
        "mbarrier.try_wait.parity.acquire.cta.shared::cta.b64 P1, [%0], %1, 0x989680;\n\t" \
        "@P1 bra.uni WD%=;\n\tbra.uni WL%=;\n\tWD%=:\n\t}" \
        :: "r"(a), "r"(par) : "memory"); } while (0)

// ============================================================
// split_w: W -> fp16 hi pairs, pair-packed: [g8][pr][n][e]
// ============================================================
__global__ __launch_bounds__(256) void split_w(
    const float* __restrict__ Wv, const float* __restrict__ Wk,
    const float* __restrict__ Wq, const float* __restrict__ Wo)
{
    const int slot = blockIdx.y;
    const float* src = (slot==0)?Wv:(slot==1)?Wk:(slot==2)?Wq:Wo;
    int i = blockIdx.x * 256 + threadIdx.x;   // 0..131071
    int kp = i >> 9, n = i & 511;
    float x0 = src[(2*kp  ) * EMB + n];
    float x1 = src[(2*kp+1) * EMB + n];
    int kg = kp >> 3, r = kp & 7;
    size_t off = (size_t)slot*131072 + (size_t)kg*4096 + (r & 3)*1024 + n*2 + (r >> 2);
    g_wh[off] = packh_hi(x0, x1);
}

// ============================================================
// fp16x2 GEMM core: ktile 32, 3-stage ring, one sync/tile.
// A stride 40 (conflict-free LDS.64); B pair-packed, stride 264.
// ============================================================
#define AST 40
#define BSTP 264
#define GA (3*128*AST)      // floats
#define GB (3*8*BSTP)       // u32
#define GEMM_SMEM ((GA + GB) * 4)

__device__ __forceinline__ void gemm_prefetch(
    const float* __restrict__ X, const uint32_t* __restrict__ Wh,
    float* As, uint32_t* Bh, int m0, int n0, int k0, int buf, int tid)
{
    #pragma unroll
    for (int it = 0; it < 4; it++) {
        int f = tid + 256 * it;
        int row = f >> 3, c4 = f & 7;
        cpa16(&As[(buf*128 + row)*AST + c4*4], X + (size_t)(m0+row)*EMB + k0 + c4*4);
    }
    // B: 8 rows x 256 u32 per tile (2 g8 groups x 4 pr)
    const size_t gbase = (size_t)(k0 >> 4) * 4096 + (size_t)n0 * 2;
    #pragma unroll
    for (int it = 0; it < 2; it++) {
        int c = tid + 256 * it;          // 0..511
        int row = c >> 6, col4 = c & 63;
        size_t gb = gbase + (size_t)(row >> 2) * 4096 + (row & 3) * 1024 + col4 * 4;
        cpa16(&Bh[(buf*8 + row)*BSTP + col4*4], Wh + gb);
    }
}

__device__ __forceinline__ void gemm_core(
    const float* __restrict__ X, const uint32_t* __restrict__ Wh,
    float* sm, float c[2][8][4], int m0, int n0, int tid)
{
    float* As = sm;
    uint32_t* Bh = (uint32_t*)(sm + GA);

    const int lane = tid & 31, w = tid >> 5;
    const int g = lane >> 2, cq = lane & 3;
    const int wm = (w & 3) * 32, wn = (w >> 2) * 64;

    #pragma unroll
    for (int mt = 0; mt < 2; mt++)
        #pragma unroll
        for (int nt = 0; nt < 8; nt++)
            #pragma unroll
            for (int e = 0; e < 4; e++) c[mt][nt][e] = 0.f;

    gemm_prefetch(X, Wh, As, Bh, m0, n0, 0, 0, tid);
    CPCOMMIT();
    gemm_prefetch(X, Wh, As, Bh, m0, n0, 32, 1, tid);
    CPCOMMIT();

    for (int t = 0; t < 16; t++) {
        CPWAIT(1);
        __syncthreads();
        if (t + 2 < 16)
            gemm_prefetch(X, Wh, As, Bh, m0, n0, (t+2)*32, (t+2)%3, tid);
        CPCOMMIT();

        const int cb = t % 3;
        const int ab = cb * 128, bb = cb * 8;
        #pragma unroll
        for (int ks = 0; ks < 2; ks++) {
            uint32_t ah[2][4], al[2][4];
            #pragma unroll
            for (int mt = 0; mt < 2; mt++) {
                int rb = ab + wm + mt*16 + g;
                int kb = ks*16 + 2*cq;
                float2 v0 = *(const float2*)&As[(rb    )*AST + kb    ];
                float2 v1 = *(const float2*)&As[(rb + 8)*AST + kb    ];
                float2 v2 = *(const float2*)&As[(rb    )*AST + kb + 8];
                float2 v3 = *(const float2*)&As[(rb + 8)*AST + kb + 8];
                split_packh(v0.x, v0.y, ah[mt][0], al[mt][0]);
                split_packh(v1.x, v1.y, ah[mt][1], al[mt][1]);
                split_packh(v2.x, v2.y, ah[mt][2], al[mt][2]);
                split_packh(v3.x, v3.y, ah[mt][3], al[mt][3]);
            }
            uint32_t bh[8][2];
            const int brow = (bb + ks*4 + cq) * BSTP;
            #pragma unroll
            for (int nt = 0; nt < 8; nt++) {
                int nn = wn + nt*8 + g;
                uint2 b2 = *(uint2*)&Bh[brow + nn*2];
                bh[nt][0] = b2.x; bh[nt][1] = b2.y;
            }
            #pragma unroll
            for (int mt = 0; mt < 2; mt++)
                #pragma unroll
                for (int nt = 0; nt < 8; nt++) {
                    mmah(c[mt][nt], ah[mt], bh[nt]);
                    mmah(c[mt][nt], al[mt], bh[nt]);
                }
        }
    }
}

// ============================================================
// Projections. Q: *0.125*log2(e), hi+lo, dp reordered.
// K: hi, dp reordered. V: hi, s-pair-packed layout.
// ============================================================
__global__ __launch_bounds__(256, 2) void proj_kernel(
    const float* __restrict__ values, const float* __restrict__ keys,
    const float* __restrict__ query)
{
    extern __shared__ float sm[];
    const int which = blockIdx.z;
    const float* X = (which == 0) ? values : (which == 1) ? keys : query;
    const uint32_t* Wh = g_wh + (size_t)which * 131072;

    const int m0 = blockIdx.y * 128, n0 = blockIdx.x * 128;
    float c[2][8][4];
    gemm_core(X, Wh, sm, c, m0, n0, threadIdx.x);

    const int lane = threadIdx.x & 31, w = threadIdx.x >> 5;
    const int g = lane >> 2, cq = lane & 3;
    const int wm = (w & 3) * 32, wn = (w >> 2) * 64;

    if (which == 2) {
        const float post = 0.125f * 1.44269504f;
        #pragma unroll
        for (int mt = 0; mt < 2; mt++)
            #pragma unroll
            for (int half = 0; half < 2; half++) {
                int row = m0 + wm + mt*16 + g + half*8;
                int n = row >> 11, s = row & 2047;
                #pragma unroll
                for (int nt = 0; nt < 8; nt++) {
                    int col = n0 + wn + nt*8 + 2*cq;
                    int h = col >> 6, d = col & 63;
                    size_t base = ((size_t)(n*H + h)*SEQ + s)*32 + reord(d >> 1);
                    uint32_t hi, lo;
                    split_packh(c[mt][nt][half*2+0]*post, c[mt][nt][half*2+1]*post, hi, lo);
                    g_qh[base] = hi; g_ql[base] = lo;
                }
            }
    } else if (which == 1) {
        #pragma unroll
        for (int mt = 0; mt < 2; mt++)
            #pragma unroll
            for (int half = 0; half < 2; half++) {
                int row = m0 + wm + mt*16 + g + half*8;
                int n = row >> 11, s = row & 2047;
                #pragma unroll
                for (int nt = 0; nt < 8; nt++) {
                    int col = n0 + wn + nt*8 + 2*cq;
                    int h = col >> 6, d = col & 63;
                    size_t base = ((size_t)(n*H + h)*SEQ + s)*32 + reord(d >> 1);
                    g_kh[base] = packh_hi(c[mt][nt][half*2+0], c[mt][nt][half*2+1]);
                }
            }
    } else {
        #pragma unroll
        for (int mt = 0; mt < 2; mt++)
            #pragma unroll
            for (int nt = 0; nt < 8; nt++) {
                float p0 = __shfl_xor_sync(0xffffffffu, c[mt][nt][0], 4);
                float p1 = __shfl_xor_sync(0xffffffffu, c[mt][nt][1], 4);
                float p2 = __shfl_xor_sync(0xffffffffu, c[mt][nt][2], 4);
                float p3 = __shfl_xor_sync(0xffffffffu, c[mt][nt][3], 4);
                if ((g & 1) == 0) {
                    int col = n0 + wn + nt*8 + 2*cq;
                    int h = col >> 6, d = col & 63;
                    #pragma unroll
                    for (int half = 0; half < 2; half++) {
                        int row = m0 + wm + mt*16 + g + half*8;   // even s
                        int n = row >> 11, s = row & 2047;
                        int sp = s >> 1;
                        size_t vbase = (size_t)(n*H + h)*(SEQ/2)*64
                                     + (size_t)(sp >> 3)*512 + (sp & 3)*128
                                     + d*2 + ((sp >> 2) & 1);
                        float m0v = c[mt][nt][half*2+0], m1v = c[mt][nt][half*2+1];
                        float q0v = (half == 0) ? p0 : p2;
                        float q1v = (half == 0) ? p1 : p3;
                        g_vh[vbase    ] = packh_hi(m0v, q0v);   // col d
                        g_vh[vbase + 2] = packh_hi(m1v, q1v);   // col d+1
                    }
                }
            }
    }
}

// ============================================================
// Output GEMM: out = g_ao @ Wo + bo
// ============================================================
__global__ __launch_bounds__(256, 2) void out_kernel(
    const float* __restrict__ bo, float* __restrict__ out)
{
    extern __shared__ float sm[];
    const int m0 = blockIdx.y * 128, n0 = blockIdx.x * 128;
    float c[2][8][4];
    gemm_core(g_ao, g_wh + (size_t)3*131072, sm, c, m0, n0, threadIdx.x);

    const int lane = threadIdx.x & 31, w = threadIdx.x >> 5;
    const int g = lane >> 2, cq = lane & 3;
    const int wm = (w & 3) * 32, wn = (w >> 2) * 64;

    #pragma unroll
    for (int mt = 0; mt < 2; mt++)
        #pragma unroll
        for (int half = 0; half < 2; half++) {
            size_t row = m0 + wm + mt*16 + g + half*8;
            #pragma unroll
            for (int nt = 0; nt < 8; nt++) {
                int col = n0 + wn + nt*8 + 2*cq;
                float2 v = make_float2(c[mt][nt][half*2+0] + bo[col],
                                       c[mt][nt][half*2+1] + bo[col+1]);
                *(float2*)&out[row * EMB + col] = v;
            }
        }
}

// ============================================================
// Flash attention: fp16x2, BQ=128, BKV=32, 4-stage mbarrier
// pipeline. K stride 40, V pair-packed 8x128 stride 136,
// all fragment loads LDS.64.
// ============================================================
#define BQF 128
#define BKV 32
#define SFL 4
#define KSTP 40
#define VSTP 136
#define NT (SEQ/BKV)
#define FK (SFL*BKV*KSTP)        // 5120 u32
#define FV (SFL*8*VSTP)          // 4352 u32
#define FL_MS (FK + FV)
#define FL_MB (FL_MS + SFL*BKV)
#define FLASH_SMEM (FL_MB*4 + 64)

__device__ __forceinline__ void flash_fill(
    const uint32_t* __restrict__ Khg, const uint32_t* __restrict__ Vhg,
    const int* __restrict__ mrow, uint32_t* Kh, uint32_t* Vh,
    int* ms, int k0, int buf, int tid)
{
    int row = tid >> 3, c4 = tid & 7;            // K: 32 rows x 32 u32
    cpa16(&Kh[(buf*BKV+row)*KSTP + c4*4], Khg + (size_t)(k0+row)*32 + c4*4);
    int vrow = tid >> 5, vc = tid & 31;          // V: 8 rows x 128 u32
    size_t gv = (size_t)(k0 >> 4) * 512 + (vrow >> 2)*512 + (vrow & 3)*128 + vc*4;
    cpa16(&Vh[(buf*8+vrow)*VSTP + vc*4], Vhg + gv);
    if (tid < 8) cpa16(&ms[buf*BKV + tid*4], mrow + k0 + tid*4);
}

__global__ __launch_bounds__(256, 2) void flash_kernel(const int* __restrict__ mask)
{
    extern __shared__ uint32_t smu[];
    uint32_t* Kh = smu;
    uint32_t* Vh = Kh + FK;
    int*      ms = (int*)(smu + FL_MS);
    const uint32_t sbF = (uint32_t)__cvta_generic_to_shared(smu);
    const uint32_t mb1 = sbF + FL_MB*4;
    const uint32_t mb2 = sbF + FL_MB*4 + 32;

    const int tid = threadIdx.x;
    const int lane = tid & 31, w = tid >> 5;
    const int g = lane >> 2, cq = lane & 3;
    const int q0 = blockIdx.x * BQF;
    const int nh = blockIdx.y;
    const int n = nh >> 3, h = nh & 7;
    const uint32_t* Qhg = g_qh + (size_t)nh * SEQ * 32;
    const uint32_t* Qlg = g_ql + (size_t)nh * SEQ * 32;
    const uint32_t* Khg = g_kh + (size_t)nh * SEQ * 32;
    const uint32_t* Vhg = g_vh + (size_t)nh * (SEQ/2) * 64;
    const int* mrow = mask + n * SEQ;
    const int rb = w * 16 + g;

    if (tid == 0) {
        #pragma unroll
        for (int s = 0; s < SFL; s++) {
            MBAR_INIT(mb1 + s*8, 256);
            MBAR_INIT(mb2 + s*8, 256);
        }
    }
    __syncthreads();

    flash_fill(Khg, Vhg, mrow, Kh, Vh, ms, 0, 0, tid);
    CPA_ARRIVE(mb1 + 0*8);
    flash_fill(Khg, Vhg, mrow, Kh, Vh, ms, BKV, 1, tid);
    CPA_ARRIVE(mb1 + 1*8);

    // Q fragments: vector LDG from reordered layout
    uint32_t qh[4][4], ql[4][4];
    {
        const size_t r0 = (size_t)(q0 + rb) * 32, r1 = r0 + 8*32;
        #pragma unroll
        for (int ks = 0; ks < 4; ks++) {
            int o = ks*8 + cq*2;
            uint2 u0 = *(const uint2*)(Qhg + r0 + o);
            uint2 u1 = *(const uint2*)(Qhg + r1 + o);
            uint2 v0 = *(const uint2*)(Qlg + r0 + o);
            uint2 v1 = *(const uint2*)(Qlg + r1 + o);
            qh[ks][0] = u0.x; qh[ks][2] = u0.y;
            qh[ks][1] = u1.x; qh[ks][3] = u1.y;
            ql[ks][0] = v0.x; ql[ks][2] = v0.y;
            ql[ks][1] = v1.x; ql[ks][3] = v1.y;
        }
    }

    float acc[8][4];
    float mi[2] = {-1e30f, -1e30f}, li[2] = {0.f, 0.f};
    #pragma unroll
    for (int nt = 0; nt < 8; nt++)
        #pragma unroll
        for (int e = 0; e < 4; e++) acc[nt][e] = 0.f;

    for (int t = 0; t < NT; t++) {
        const int f = t + 2;
        if (f < NT) {
            const int s = f & 3;
            if (t >= 2) MBAR_WAIT(mb2 + s*8, ((t - 2) >> 2) & 1);
            flash_fill(Khg, Vhg, mrow, Kh, Vh, ms, f*BKV, s, tid);
            CPA_ARRIVE(mb1 + s*8);
        }

        const int cb = t & 3;
        MBAR_WAIT(mb1 + cb*8, (t >> 2) & 1);

        const uint32_t* KhC = Kh + cb * BKV * KSTP;
        const uint32_t* VhC = Vh + cb * 8 * VSTP;
        const int*      msC = ms + cb * BKV;

        // ---- S = Q @ K^T ----
        float s[4][4];
        #pragma unroll
        for (int nt = 0; nt < 4; nt++)
            #pragma unroll
            for (int e = 0; e < 4; e++) s[nt][e] = 0.f;

        #pragma unroll
        for (int ks = 0; ks < 4; ks++) {
            const int koff = ks*8 + cq*2;
            uint32_t bh[4][2];
            #pragma unroll
            for (int nt = 0; nt < 4; nt++) {
                int nn = nt*8 + g;
                uint2 b2 = *(uint2*)&KhC[nn*KSTP + koff];
                bh[nt][0] = b2.x; bh[nt][1] = b2.y;
            }
            #pragma unroll
            for (int nt = 0; nt < 4; nt++) {
                mmah(s[nt], qh[ks], bh[nt]);
                mmah(s[nt], ql[ks], bh[nt]);
            }
        }

        // ---- mask + online softmax (base-2) ----
        float mx0 = -1e30f, mx1 = -1e30f;
        #pragma unroll
        for (int nt = 0; nt < 4; nt++) {
            #pragma unroll
            for (int j = 0; j < 2; j++) {
                int mv = msC[nt*8 + 2*cq + j];
                float v0 = mv ? s[nt][j]   : -1e30f;
                float v1 = mv ? s[nt][2+j] : -1e30f;
                s[nt][j] = v0; s[nt][2+j] = v1;
                mx0 = fmaxf(mx0, v0); mx1 = fmaxf(mx1, v1);
            }
        }
        mx0 = fmaxf(mx0, __shfl_xor_sync(0xffffffffu, mx0, 1));
        mx0 = fmaxf(mx0, __shfl_xor_sync(0xffffffffu, mx0, 2));
        mx1 = fmaxf(mx1, __shfl_xor_sync(0xffffffffu, mx1, 1));
        mx1 = fmaxf(mx1, __shfl_xor_sync(0xffffffffu, mx1, 2));

        float mn0 = fmaxf(mi[0], mx0), mn1 = fmaxf(mi[1], mx1);
        float cr0 = ex2f(mi[0] - mn0), cr1 = ex2f(mi[1] - mn1);
        float sum0 = 0.f, sum1 = 0.f;
        #pragma unroll
        for (int nt = 0; nt < 4; nt++) {
            s[nt][0] = ex2f(s[nt][0] - mn0);
            s[nt][1] = ex2f(s[nt][1] - mn0);
            s[nt][2] = ex2f(s[nt][2] - mn1);
            s[nt][3] = ex2f(s[nt][3] - mn1);
            sum0 += s[nt][0] + s[nt][1];
            sum1 += s[nt][2] + s[nt][3];
        }
        sum0 += __shfl_xor_sync(0xffffffffu, sum0, 1);
        sum0 += __shfl_xor_sync(0xffffffffu, sum0, 2);
        sum1 += __shfl_xor_sync(0xffffffffu, sum1, 1);
        sum1 += __shfl_xor_sync(0xffffffffu, sum1, 2);
        li[0] = li[0] * cr0 + sum0; mi[0] = mn0;
        li[1] = li[1] * cr1 + sum1; mi[1] = mn1;
        #pragma unroll
        for (int nt = 0; nt < 8; nt++) {
            acc[nt][0] *= cr0; acc[nt][1] *= cr0;
            acc[nt][2] *= cr1; acc[nt][3] *= cr1;
        }

        // ---- P fragments: register repack, hi+lo ----
        uint32_t ph[2][4], pl[2][4];
        #pragma unroll
        for (int k2 = 0; k2 < 2; k2++) {
            split_packh(s[2*k2  ][0], s[2*k2  ][1], ph[k2][0], pl[k2][0]);
            split_packh(s[2*k2  ][2], s[2*k2  ][3], ph[k2][1], pl[k2][1]);
            split_packh(s[2*k2+1][0], s[2*k2+1][1], ph[k2][2], pl[k2][2]);
            split_packh(s[2*k2+1][2], s[2*k2+1][3], ph[k2][3], pl[k2][3]);
        }

        // ---- O += P @ V (V pair-packed: uint2 per fragment) ----
        #pragma unroll
        for (int k2 = 0; k2 < 2; k2++) {
            const int vrow = (k2*4 + cq) * VSTP;
            uint32_t vh[8][2];
            #pragma unroll
            for (int nt = 0; nt < 8; nt++) {
                int dd = nt*8 + g;
                uint2 v2 = *(uint2*)&VhC[vrow + dd*2];
                vh[nt][0] = v2.x; vh[nt][1] = v2.y;
            }
            #pragma unroll
            for (int nt = 0; nt < 8; nt++) {
                mmah(acc[nt], ph[k2], vh[nt]);
                mmah(acc[nt], pl[k2], vh[nt]);
            }
        }

        MBAR_ARRIVE(mb2 + cb*8);
    }

    float inv0 = 1.f / li[0], inv1 = 1.f / li[1];
    #pragma unroll
    for (int nt = 0; nt < 8; nt++) {
        int col = h * 64 + nt * 8 + 2 * cq;
        size_t r0 = (size_t)(n * SEQ + q0 + rb) * EMB + col;
        size_t r1 = (size_t)(n * SEQ + q0 + rb + 8) * EMB + col;
        *(float2*)&g_ao[r0] = make_float2(acc[nt][0]*inv0, acc[nt][1]*inv0);
        *(float2*)&g_ao[r1] = make_float2(acc[nt][2]*inv1, acc[nt][3]*inv1);
    }
}

// ============================================================
extern "C" void kernel_launch(void* const* d_in, const int* in_sizes, int n_in,
                              void* d_out, int out_size)
{
    const float* values = (const float*)d_in[0];
    const float* keys   = (const float*)d_in[1];
    const float* query  = (const float*)d_in[2];
    const int*   mask   = (const int*)  d_in[3];
    const float* Wv     = (const float*)d_in[4];
    const float* Wk     = (const float*)d_in[5];
    const float* Wq     = (const float*)d_in[6];
    const float* Wo     = (const float*)d_in[7];
    const float* bo     = (const float*)d_in[8];

    split_w<<<dim3(EMB*EMB/2/256, 4), 256>>>(Wv, Wk, Wq, Wo);

    cudaFuncSetAttribute(proj_kernel, cudaFuncAttributeMaxDynamicSharedMemorySize, GEMM_SMEM);
    proj_kernel<<<dim3(EMB/128, NROWS/128, 3), 256, GEMM_SMEM>>>(values, keys, query);

    cudaFuncSetAttribute(flash_kernel, cudaFuncAttributeMaxDynamicSharedMemorySize, FLASH_SMEM);
    flash_kernel<<<dim3(SEQ/BQF, NH), 256, FLASH_SMEM>>>(mask);

    cudaFuncSetAttribute(out_kernel, cudaFuncAttributeMaxDynamicSharedMemorySize, GEMM_SMEM);
    out_kernel<<<dim3(EMB/128, NROWS/128), 256, GEMM_SMEM>>>(bo, (float*)d_out);
}